// round 9
// baseline (speedup 1.0000x reference)
#include <cuda_runtime.h>
#include <cuda_fp16.h>
#include <math.h>
#include <stdint.h>

#define BB 64
#define NN 1024
#define DD 512
#define CC 512
#define KTOP 16
#define INV_TEMP (1.0f/0.07f)

// ---------------- scratch (device globals: no allocations allowed) ----------
__device__ __half g_aff[(size_t)BB * CC * NN];    // [b][c][n] normalized softmax p (fp16)
__device__ float g_rnt[CC];
__device__ float g_rnc[BB];
__device__ __half g_txh[(size_t)CC*DD];           // text fp16

// ================= helpers ====================================================
static __device__ __forceinline__ uint32_t smem_u32(const void* p){
    uint32_t a;
    asm("{ .reg .u64 t; cvta.to.shared.u64 t, %1; cvt.u32.u64 %0, t; }" : "=r"(a) : "l"(p));
    return a;
}
static __device__ __forceinline__ void cpasync16(uint32_t dst, const void* src){
    asm volatile("cp.async.cg.shared.global [%0], [%1], 16;" :: "r"(dst), "l"(src) : "memory");
}
static __device__ __forceinline__ void ldsm4(uint32_t &r0, uint32_t &r1,
                                             uint32_t &r2, uint32_t &r3, uint32_t addr){
    asm volatile("ldmatrix.sync.aligned.m8n8.x4.shared.b16 {%0,%1,%2,%3}, [%4];"
        : "=r"(r0), "=r"(r1), "=r"(r2), "=r"(r3) : "r"(addr));
}
static __device__ __forceinline__ void mma16816(float* d, const uint32_t* a,
                                                uint32_t b0, uint32_t b1){
    asm volatile("mma.sync.aligned.m16n8k16.row.col.f32.f16.f16.f32 "
        "{%0,%1,%2,%3}, {%4,%5,%6,%7}, {%8,%9}, {%0,%1,%2,%3};"
        : "+f"(d[0]), "+f"(d[1]), "+f"(d[2]), "+f"(d[3])
        : "r"(a[0]), "r"(a[1]), "r"(a[2]), "r"(a[3]), "r"(b0), "r"(b1));
}

// ================= kernel 1: text fp16 convert + text/cls L2 norms ===========
__global__ void convert_kernel(const float* __restrict__ vcls,
                               const float* __restrict__ text){
    int w    = (blockIdx.x * blockDim.x + threadIdx.x) >> 5;
    int lane = threadIdx.x & 31;
    const int NW = CC + BB;
    if (w >= NW) return;
    const float* src; __half* hi = nullptr; float* rdst;
    if (w < CC){ src = text + (size_t)w*DD; hi = g_txh + (size_t)w*DD; rdst = g_rnt + w; }
    else       { int ci = w - CC; src = vcls + (size_t)ci*DD; rdst = g_rnc + ci; }
    float ss = 0.f;
    #pragma unroll
    for (int j = 0; j < 4; j++){
        int o = (j*32 + lane) * 4;
        float4 v = *reinterpret_cast<const float4*>(src + o);
        ss += v.x*v.x + v.y*v.y + v.z*v.z + v.w*v.w;
        if (hi){
            union { __half2 h2[2]; uint2 u; } P;
            P.h2[0] = __floats2half2_rn(v.x, v.y);
            P.h2[1] = __floats2half2_rn(v.z, v.w);
            *reinterpret_cast<uint2*>(hi + o) = P.u;
        }
    }
    #pragma unroll
    for (int off = 16; off; off >>= 1) ss += __shfl_xor_sync(0xffffffffu, ss, off);
    if (lane == 0) *rdst = 1.0f / fmaxf(sqrtf(ss), 1e-12f);
}

// ================= kernel 2: global affinity, writes 0.3*softmax ============
__global__ __launch_bounds__(512) void affg_kernel(const float* __restrict__ vcls,
                                                   const float* __restrict__ text,
                                                   float* __restrict__ out){
    __shared__ float sv[DD];
    __shared__ float red[16];
    int b = blockIdx.x, tid = threadIdx.x;
    sv[tid] = vcls[b*DD + tid];
    __syncthreads();
    const float* t = text + (size_t)tid * DD;
    float dot = 0.f;
    #pragma unroll 4
    for (int k = 0; k < DD; k += 4){
        float4 v = *reinterpret_cast<const float4*>(t + k);
        dot += v.x*sv[k] + v.y*sv[k+1] + v.z*sv[k+2] + v.w*sv[k+3];
    }
    float logit = dot * g_rnc[b] * g_rnt[tid] * INV_TEMP;
    int lane = tid & 31, wid = tid >> 5;
    float m = logit;
    #pragma unroll
    for (int off = 16; off; off >>= 1) m = fmaxf(m, __shfl_xor_sync(0xffffffffu, m, off));
    if (lane == 0) red[wid] = m;
    __syncthreads();
    float bm = red[0];
    #pragma unroll
    for (int i = 1; i < 16; i++) bm = fmaxf(bm, red[i]);
    __syncthreads();
    float e = __expf(logit - bm);
    float s = e;
    #pragma unroll
    for (int off = 16; off; off >>= 1) s += __shfl_xor_sync(0xffffffffu, s, off);
    if (lane == 0) red[wid] = s;
    __syncthreads();
    float bs = 0.f;
    #pragma unroll
    for (int i = 0; i < 16; i++) bs += red[i];
    out[b*CC + tid] = 0.3f * e / bs;
}

// ================= kernel 3: fp16 HMMA GEMM, 2 CTAs/SM =======================
// CTA: 32 patches x 512 classes, 256 threads (8 warps, nw=wid), warp tile 32x64.
// kc=32, 16 k-iters, stride-80 unswizzled tiles (conflict-free for ldmatrix).
#define SM_A0   0u
#define SM_A1   2560u
#define SM_B0   5120u
#define SM_B1   46080u
#define SM_AUX  87040u
#define SM_DYN  90624u

static __device__ __forceinline__ void issueB(int kt, uint32_t b_dst, int tid){
    const __half* Bb = g_txh + kt * 32;
    #pragma unroll
    for (int i = 0; i < 8; i++){   // B: 512 rows x 64B = 2048 16B-chunks
        int g = tid + i*256; int row = g >> 2; int c = g & 3;
        cpasync16(b_dst + (uint32_t)(row*80 + c*16), Bb + (size_t)row*DD + c*8);
    }
    asm volatile("cp.async.commit_group;" ::: "memory");
}

// convert & store one thread's float4 of A (row rowA, 16B chunk cA of the
// 128B f32 slab), accumulate sumsq
static __device__ __forceinline__ void stsA(uint32_t abase, int rowA, int cA,
                                            float4 pf, float& ss){
    union { __half2 h2; uint32_t u; } P0, P1;
    P0.h2 = __floats2half2_rn(pf.x, pf.y);
    P1.h2 = __floats2half2_rn(pf.z, pf.w);
    ss += pf.x*pf.x + pf.y*pf.y + pf.z*pf.z + pf.w*pf.w;
    asm volatile("st.shared.v2.b32 [%0], {%1,%2};"
        :: "r"(abase + (uint32_t)(rowA*80 + cA*8)), "r"(P0.u), "r"(P1.u) : "memory");
}

__global__ __launch_bounds__(256, 2) void gemm_softmax_kernel(const float* __restrict__ vp){
    extern __shared__ __align__(16) char dsm[];
    const uint32_t raw  = smem_u32(dsm);
    const uint32_t base = (raw + 1023u) & ~1023u;
    char* bp = dsm + (base - raw);

    const int tid = threadIdx.x;
    const int pb  = blockIdx.x;          // 0..2047
    const int b   = pb >> 5;
    const int nt  = pb & 31;

    const uint32_t ab[2]   = { base + SM_A0, base + SM_A1 };
    const uint32_t bbuf[2] = { base + SM_B0, base + SM_B1 };
    float* s_t    = reinterpret_cast<float*>(bp);                    // 512*33 f (overlays stages)
    float* s_rnt  = reinterpret_cast<float*>(bp + SM_AUX);           // 512 f
    float* s_rnp  = reinterpret_cast<float*>(bp + SM_AUX + 2048);    // 32 f
    float* s_red  = reinterpret_cast<float*>(bp + SM_AUX + 2176);    // 32*8 f
    float* s_gmax = reinterpret_cast<float*>(bp + SM_AUX + 3200);    // 32 f
    float* s_rzv  = reinterpret_cast<float*>(bp + SM_AUX + 3328);    // 32 f

    const int wid  = tid >> 5;           // 0..7 = n-warp
    const int lane = tid & 31;
    const int nw   = wid;
    const int gid  = lane >> 2;          // row group 0..7
    const int tig  = lane & 3;

    s_rnt[tid] = g_rnt[tid]; s_rnt[tid+256] = g_rnt[tid+256];

    // fused A path: thread owns (rowA = tid>>3, 16B chunk cA = tid&7) of each
    // 32x32f32 slab -> coalesced 128B row segments
    const int rowA = tid >> 3;
    const int cA   = tid & 7;
    const float* Ag = vp + ((size_t)(pb*32 + rowA))*DD + cA*4;

    float4 pf = *reinterpret_cast<const float4*>(Ag);

    issueB(0, bbuf[0], tid);
    issueB(1, bbuf[1], tid);

    float ss = 0.f;
    stsA(ab[0], rowA, cA, pf, ss);                        // A tile for kt=0
    pf = *reinterpret_cast<const float4*>(Ag + 32);

    // ldmatrix lane addressing (canonical x4 fragment order)
    const int lr = (lane & 7) + ((lane >> 3) & 1) * 8;   // row within 16
    const int lk = (lane >> 4) * 16;                     // 16B col half

    float acc[2][8][4];
    #pragma unroll
    for (int mi = 0; mi < 2; mi++)
        #pragma unroll
        for (int j = 0; j < 8; j++)
            #pragma unroll
            for (int v = 0; v < 4; v++) acc[mi][j][v] = 0.f;

    for (int it = 0; it < 16; ++it){
        const int cur = it & 1;
        if (it == 15) asm volatile("cp.async.wait_group 0;" ::: "memory");
        else          asm volatile("cp.async.wait_group 1;" ::: "memory");
        __syncthreads();

        const uint32_t abase = ab[cur];
        const uint32_t bbase = bbuf[cur];
        #pragma unroll
        for (int ks = 0; ks < 2; ks++){
            uint32_t af[2][4];
            #pragma unroll
            for (int mi = 0; mi < 2; mi++){
                int r = mi*16 + lr;
                ldsm4(af[mi][0], af[mi][1], af[mi][2], af[mi][3],
                      abase + (uint32_t)(r*80 + ks*32 + lk));
            }
            uint32_t bf[4][4];
            #pragma unroll
            for (int jj = 0; jj < 4; jj++){
                int r = nw*64 + jj*16 + lr;
                ldsm4(bf[jj][0], bf[jj][1], bf[jj][2], bf[jj][3],
                      bbase + (uint32_t)(r*80 + ks*32 + lk));
            }
            #pragma unroll
            for (int mi = 0; mi < 2; mi++)
                #pragma unroll
                for (int j = 0; j < 8; j++)
                    mma16816(acc[mi][j], af[mi], bf[j>>1][j&1], bf[j>>1][(j&1)+2]);
        }
        __syncthreads();
        if (it + 1 < 16) stsA(ab[(it+1)&1], rowA, cA, pf, ss);   // A tile for kt=it+1
        if (it + 2 < 16){
            pf = *reinterpret_cast<const float4*>(Ag + (it+2)*32);
            issueB(it + 2, bbuf[cur], tid);
        }
    }

    // patch norms: reduce sumsq over the 8-lane group sharing each row
    ss += __shfl_xor_sync(0xffffffffu, ss, 1);
    ss += __shfl_xor_sync(0xffffffffu, ss, 2);
    ss += __shfl_xor_sync(0xffffffffu, ss, 4);
    if (cA == 0) s_rnp[rowA] = 1.0f / fmaxf(sqrtf(ss), 1e-12f);
    __syncthreads();

    // ---- epilogue: scale, softmax over full 512 cols, normalized fp16 store
    float rs[2][2], rt[8][2];
    #pragma unroll
    for (int mi = 0; mi < 2; mi++)
        #pragma unroll
        for (int h = 0; h < 2; h++)
            rs[mi][h] = s_rnp[mi*16 + h*8 + gid] * INV_TEMP;
    #pragma unroll
    for (int j = 0; j < 8; j++){
        int c0 = nw*64 + j*8 + tig*2;
        rt[j][0] = s_rnt[c0]; rt[j][1] = s_rnt[c0+1];
    }
    #pragma unroll
    for (int mi = 0; mi < 2; mi++)
        #pragma unroll
        for (int j = 0; j < 8; j++)
            #pragma unroll
            for (int v = 0; v < 4; v++)
                acc[mi][j][v] *= rs[mi][v>>1] * rt[j][v&1];

    // per-row max (warp slice over its 64 cols), quad shuffle, 8-warp smem reduce
    #pragma unroll
    for (int mi = 0; mi < 2; mi++)
        #pragma unroll
        for (int h = 0; h < 2; h++){
            float mx = -3.0e38f;
            #pragma unroll
            for (int j = 0; j < 8; j++)
                mx = fmaxf(mx, fmaxf(acc[mi][j][2*h], acc[mi][j][2*h+1]));
            mx = fmaxf(mx, __shfl_xor_sync(0xffffffffu, mx, 1));
            mx = fmaxf(mx, __shfl_xor_sync(0xffffffffu, mx, 2));
            if (tig == 0) s_red[(mi*16 + h*8 + gid)*8 + nw] = mx;
        }
    __syncthreads();
    if (tid < 32){
        float m = s_red[tid*8];
        #pragma unroll
        for (int k = 1; k < 8; k++) m = fmaxf(m, s_red[tid*8 + k]);
        s_gmax[tid] = m;
    }
    __syncthreads();

    // exp + row sum
    #pragma unroll
    for (int mi = 0; mi < 2; mi++)
        #pragma unroll
        for (int h = 0; h < 2; h++){
            float gm = s_gmax[mi*16 + h*8 + gid];
            float sm = 0.f;
            #pragma unroll
            for (int j = 0; j < 8; j++){
                float e0 = __expf(acc[mi][j][2*h]   - gm);
                float e1 = __expf(acc[mi][j][2*h+1] - gm);
                acc[mi][j][2*h] = e0; acc[mi][j][2*h+1] = e1;
                sm += e0 + e1;
            }
            sm += __shfl_xor_sync(0xffffffffu, sm, 1);
            sm += __shfl_xor_sync(0xffffffffu, sm, 2);
            if (tig == 0) s_red[(mi*16 + h*8 + gid)*8 + nw] = sm;
        }
    __syncthreads();
    if (tid < 32){
        float s = 0.f;
        #pragma unroll
        for (int k = 0; k < 8; k++) s += s_red[tid*8 + k];
        s_rzv[tid] = 1.0f / s;
    }
    __syncthreads();

    // normalized transposed store into padded smem [c][n], stride 33 (overlays stages)
    #pragma unroll
    for (int mi = 0; mi < 2; mi++)
        #pragma unroll
        for (int j = 0; j < 8; j++)
            #pragma unroll
            for (int v = 0; v < 4; v++){
                int col = nw*64 + j*8 + tig*2 + (v&1);
                int row = mi*16 + (v>>1)*8 + gid;
                s_t[col*33 + row] = acc[mi][j][v] * s_rzv[row];
            }
    __syncthreads();

    // copy-out: g_aff[b][c][nt*32 + n], 64B per column, 2 cols per thread
    __half* obase = g_aff + (size_t)b * CC * NN + (size_t)nt * 32;
    #pragma unroll
    for (int q = 0; q < 2; q++){
        int c = tid + q*256;
        const float* src = &s_t[c*33];
        union { __half2 h[16]; uint4 u4[4]; } U;
        #pragma unroll
        for (int n2 = 0; n2 < 16; n2++)
            U.h[n2] = __floats2half2_rn(src[2*n2], src[2*n2+1]);
        uint4* dst = reinterpret_cast<uint4*>(obase + (size_t)c * NN);
        #pragma unroll
        for (int x = 0; x < 4; x++) dst[x] = U.u4[x];
    }
}

// ================= kernel 4: top-16 over N per (b,c), blend ==================
// key = (fp16bits << 16) | (lane << 3) | chunk : one redux gives value+owner+chunk
__global__ void topk_kernel(float* __restrict__ out){
    int w    = (blockIdx.x * blockDim.x + threadIdx.x) >> 5;  // b*512 + c
    int lane = threadIdx.x & 31;
    if (w >= BB*CC) return;
    const uint4* p = reinterpret_cast<const uint4*>(g_aff + (size_t)w * NN);

    unsigned v[32], ck[8];
    #pragma unroll
    for (int j = 0; j < 4; j++){
        uint4 q = p[j*32 + lane];
        v[8*j+0] = q.x & 0xFFFFu; v[8*j+1] = q.x >> 16;
        v[8*j+2] = q.y & 0xFFFFu; v[8*j+3] = q.y >> 16;
        v[8*j+4] = q.z & 0xFFFFu; v[8*j+5] = q.z >> 16;
        v[8*j+6] = q.w & 0xFFFFu; v[8*j+7] = q.w >> 16;
    }
    #pragma unroll
    for (int c = 0; c < 8; c++){
        unsigned m0 = v[4*c]   > v[4*c+1] ? v[4*c]   : v[4*c+1];
        unsigned m1 = v[4*c+2] > v[4*c+3] ? v[4*c+2] : v[4*c+3];
        unsigned mv = m0 > m1 ? m0 : m1;
        ck[c] = (mv << 16) | ((unsigned)lane << 3) | (unsigned)c;
    }
    unsigned lk = ck[0];
    #pragma unroll
    for (int c = 1; c < 8; c++) lk = ck[c] > lk ? ck[c] : lk;

    float sum = 0.f;
    #pragma unroll
    for (int it = 0; it < KTOP; ++it){
        unsigned m;
        asm("redux.sync.max.u32 %0, %1, 0xffffffff;" : "=r"(m) : "r"(lk));
        __half_raw hr; hr.x = (unsigned short)(m >> 16);
        sum += __half2float(*reinterpret_cast<__half*>(&hr));
        if (((m >> 3) & 31u) == (unsigned)lane){
            unsigned val = m >> 16;
            int oc = (int)(m & 7u);
            #pragma unroll
            for (int c = 0; c < 8; c++) if (c == oc){
                if      (v[4*c]   == val) v[4*c]   = 0u;
                else if (v[4*c+1] == val) v[4*c+1] = 0u;
                else if (v[4*c+2] == val) v[4*c+2] = 0u;
                else                      v[4*c+3] = 0u;
                unsigned m0 = v[4*c]   > v[4*c+1] ? v[4*c]   : v[4*c+1];
                unsigned m1 = v[4*c+2] > v[4*c+3] ? v[4*c+2] : v[4*c+3];
                unsigned mv = m0 > m1 ? m0 : m1;
                ck[c] = (mv << 16) | ((unsigned)lane << 3) | (unsigned)c;
            }
            lk = ck[0];
            #pragma unroll
            for (int c = 1; c < 8; c++) lk = ck[c] > lk ? ck[c] : lk;
        }
    }
    if (lane == 0) out[w] += 0.7f * (sum * (1.0f / (float)KTOP));
}

// ================= launch =====================================================
extern "C" void kernel_launch(void* const* d_in, const int* in_sizes, int n_in,
                              void* d_out, int out_size){
    const float* vcls = nullptr;
    const float* vp   = nullptr;
    const float* text = nullptr;
    for (int i = 0; i < n_in; i++){
        if      (in_sizes[i] == BB*DD)     vcls = (const float*)d_in[i];
        else if (in_sizes[i] == BB*NN*DD)  vp   = (const float*)d_in[i];
        else if (in_sizes[i] == CC*DD)     text = (const float*)d_in[i];
    }
    float* out = (float*)d_out;

    cudaFuncSetAttribute(gemm_softmax_kernel,
                         cudaFuncAttributeMaxDynamicSharedMemorySize, SM_DYN);

    const int nwarps = CC + BB;
    convert_kernel<<<(nwarps*32 + 255)/256, 256>>>(vcls, text);
    affg_kernel<<<BB, 512>>>(vcls, text, out);
    gemm_softmax_kernel<<<2048, 256, SM_DYN>>>(vp);
    topk_kernel<<<(BB*CC*32 + 255)/256, 256>>>(out);
}

// round 10
// speedup vs baseline: 1.1307x; 1.1307x over previous
#include <cuda_runtime.h>
#include <cuda_fp16.h>
#include <math.h>
#include <stdint.h>

#define BB 64
#define NN 1024
#define DD 512
#define CC 512
#define KTOP 16
#define INV_TEMP (1.0f/0.07f)

// ---------------- scratch (device globals: no allocations allowed) ----------
__device__ __half g_aff[(size_t)BB * CC * NN];    // [b][c][n] normalized softmax p (fp16)
__device__ float g_rnt[CC];
__device__ float g_rnc[BB];
__device__ __half g_txh[(size_t)CC*DD];           // text fp16

// ================= helpers ====================================================
static __device__ __forceinline__ uint32_t smem_u32(const void* p){
    uint32_t a;
    asm("{ .reg .u64 t; cvta.to.shared.u64 t, %1; cvt.u32.u64 %0, t; }" : "=r"(a) : "l"(p));
    return a;
}
static __device__ __forceinline__ void cpasync16(uint32_t dst, const void* src){
    asm volatile("cp.async.cg.shared.global [%0], [%1], 16;" :: "r"(dst), "l"(src) : "memory");
}
static __device__ __forceinline__ uint32_t swz(uint32_t o){ return o ^ ((o >> 3) & 0x70u); }

static __device__ __forceinline__ void ldsm4(uint32_t &r0, uint32_t &r1,
                                             uint32_t &r2, uint32_t &r3, uint32_t addr){
    asm volatile("ldmatrix.sync.aligned.m8n8.x4.shared.b16 {%0,%1,%2,%3}, [%4];"
        : "=r"(r0), "=r"(r1), "=r"(r2), "=r"(r3) : "r"(addr));
}
static __device__ __forceinline__ void mma16816(float* d, const uint32_t* a,
                                                uint32_t b0, uint32_t b1){
    asm volatile("mma.sync.aligned.m16n8k16.row.col.f32.f16.f16.f32 "
        "{%0,%1,%2,%3}, {%4,%5,%6,%7}, {%8,%9}, {%0,%1,%2,%3};"
        : "+f"(d[0]), "+f"(d[1]), "+f"(d[2]), "+f"(d[3])
        : "r"(a[0]), "r"(a[1]), "r"(a[2]), "r"(a[3]), "r"(b0), "r"(b1));
}

// ================= kernel 1: text fp16 convert + text/cls L2 norms ===========
__global__ void convert_kernel(const float* __restrict__ vcls,
                               const float* __restrict__ text){
    int w    = (blockIdx.x * blockDim.x + threadIdx.x) >> 5;
    int lane = threadIdx.x & 31;
    const int NW = CC + BB;
    if (w >= NW) return;
    const float* src; __half* hi = nullptr; float* rdst;
    if (w < CC){ src = text + (size_t)w*DD; hi = g_txh + (size_t)w*DD; rdst = g_rnt + w; }
    else       { int ci = w - CC; src = vcls + (size_t)ci*DD; rdst = g_rnc + ci; }
    float ss = 0.f;
    #pragma unroll
    for (int j = 0; j < 4; j++){
        int o = (j*32 + lane) * 4;
        float4 v = *reinterpret_cast<const float4*>(src + o);
        ss += v.x*v.x + v.y*v.y + v.z*v.z + v.w*v.w;
        if (hi){
            union { __half2 h2[2]; uint2 u; } P;
            P.h2[0] = __floats2half2_rn(v.x, v.y);
            P.h2[1] = __floats2half2_rn(v.z, v.w);
            *reinterpret_cast<uint2*>(hi + o) = P.u;
        }
    }
    #pragma unroll
    for (int off = 16; off; off >>= 1) ss += __shfl_xor_sync(0xffffffffu, ss, off);
    if (lane == 0) *rdst = 1.0f / fmaxf(sqrtf(ss), 1e-12f);
}

// ================= kernel 2: global affinity, writes 0.3*softmax ============
__global__ __launch_bounds__(512) void affg_kernel(const float* __restrict__ vcls,
                                                   const float* __restrict__ text,
                                                   float* __restrict__ out){
    __shared__ float sv[DD];
    __shared__ float red[16];
    int b = blockIdx.x, tid = threadIdx.x;
    sv[tid] = vcls[b*DD + tid];
    __syncthreads();
    const float* t = text + (size_t)tid * DD;
    float dot = 0.f;
    #pragma unroll 4
    for (int k = 0; k < DD; k += 4){
        float4 v = *reinterpret_cast<const float4*>(t + k);
        dot += v.x*sv[k] + v.y*sv[k+1] + v.z*sv[k+2] + v.w*sv[k+3];
    }
    float logit = dot * g_rnc[b] * g_rnt[tid] * INV_TEMP;
    int lane = tid & 31, wid = tid >> 5;
    float m = logit;
    #pragma unroll
    for (int off = 16; off; off >>= 1) m = fmaxf(m, __shfl_xor_sync(0xffffffffu, m, off));
    if (lane == 0) red[wid] = m;
    __syncthreads();
    float bm = red[0];
    #pragma unroll
    for (int i = 1; i < 16; i++) bm = fmaxf(bm, red[i]);
    __syncthreads();
    float e = __expf(logit - bm);
    float s = e;
    #pragma unroll
    for (int off = 16; off; off >>= 1) s += __shfl_xor_sync(0xffffffffu, s, off);
    if (lane == 0) red[wid] = s;
    __syncthreads();
    float bs = 0.f;
    #pragma unroll
    for (int i = 0; i < 16; i++) bs += red[i];
    out[b*CC + tid] = 0.3f * e / bs;
}

// ================= kernel 3: fp16 HMMA GEMM, 3-stage pipeline ================
// CTA: 64 patches x 512 classes, 256 threads (8 warps, nw=wid), warp tile 64x64.
// kc=64. B triple-buffered, A double-buffered; ONE barrier per k-iter.
#define SM_A0   0u
#define SM_A1   8192u
#define SM_B0   16384u
#define SM_B1   81920u
#define SM_B2   147456u
#define SM_AUX  212992u
#define SM_DYN  (212992u + 4864u + 1024u)

static __device__ __forceinline__ void issueB(int kt, uint32_t b_dst, int tid){
    const __half* Bb = g_txh + kt * 64;
    #pragma unroll
    for (int t = 0; t < 16; t++){  // B: 512 rows x 128B = 4096 chunks
        int g = tid + t*256; int row = g >> 3; int c16 = g & 7;
        cpasync16(b_dst + swz(row*128 + c16*16), Bb + (size_t)row*DD + c16*8);
    }
    asm volatile("cp.async.commit_group;" ::: "memory");
}

// store 4 rows' worth of converted A (rows rbase+16i, 16B chunk c16 of f32 slab)
static __device__ __forceinline__ void stsA(uint32_t abase, int rbase, int c16,
                                            const float4* pf, float* ss){
    #pragma unroll
    for (int i = 0; i < 4; i++){
        union { __half2 h2; uint32_t u; } P0, P1;
        P0.h2 = __floats2half2_rn(pf[i].x, pf[i].y);
        P1.h2 = __floats2half2_rn(pf[i].z, pf[i].w);
        ss[i] += pf[i].x*pf[i].x + pf[i].y*pf[i].y + pf[i].z*pf[i].z + pf[i].w*pf[i].w;
        uint32_t off = (uint32_t)((rbase + 16*i)*128 + c16*8);
        asm volatile("st.shared.v2.b32 [%0], {%1,%2};"
            :: "r"(abase + swz(off)), "r"(P0.u), "r"(P1.u) : "memory");
    }
}

__global__ __launch_bounds__(256, 1) void gemm_softmax_kernel(const float* __restrict__ vp){
    extern __shared__ __align__(16) char dsm[];
    const uint32_t raw  = smem_u32(dsm);
    const uint32_t base = (raw + 1023u) & ~1023u;
    char* bp = dsm + (base - raw);

    const int tid = threadIdx.x;
    const int pb  = blockIdx.x;          // 0..1023
    const int b   = pb >> 4;
    const int nt  = pb & 15;

    const uint32_t ab[2]   = { base + SM_A0, base + SM_A1 };
    const uint32_t bbuf[3] = { base + SM_B0, base + SM_B1, base + SM_B2 };
    float* s_t    = reinterpret_cast<float*>(bp);                    // 512*68 f (overlays stages)
    float* s_rnt  = reinterpret_cast<float*>(bp + SM_AUX);           // 512 f
    float* s_rnp  = reinterpret_cast<float*>(bp + SM_AUX + 2048);    // 64 f
    float* s_red  = reinterpret_cast<float*>(bp + SM_AUX + 2304);    // 64*8 f
    float* s_gmax = reinterpret_cast<float*>(bp + SM_AUX + 4352);    // 64 f
    float* s_rzv  = reinterpret_cast<float*>(bp + SM_AUX + 4608);    // 64 f

    const int wid  = tid >> 5;           // 0..7 = n-warp
    const int lane = tid & 31;
    const int nw   = wid;
    const int gid  = lane >> 2;          // row group 0..7
    const int tig  = lane & 3;

    s_rnt[tid] = g_rnt[tid]; s_rnt[tid+256] = g_rnt[tid+256];

    // fused A path: lane group covers a contiguous 256B row segment
    const int c16 = tid & 15;            // 16B chunk within 64-float slab row
    const int rb  = tid >> 4;            // base row 0..15 (rows rb+16i)
    const float* Ag = vp + ((size_t)(pb*64 + rb))*DD + c16*4;

    float4 pf[4];
    #pragma unroll
    for (int i = 0; i < 4; i++)
        pf[i] = *reinterpret_cast<const float4*>(Ag + (size_t)i*16*DD);

    issueB(0, bbuf[0], tid);
    issueB(1, bbuf[1], tid);

    float ss[4] = {0.f, 0.f, 0.f, 0.f};
    stsA(ab[0], rb, c16, pf, ss);                        // A tile for kt=0
    #pragma unroll
    for (int i = 0; i < 4; i++)
        pf[i] = *reinterpret_cast<const float4*>(Ag + (size_t)i*16*DD + 64);

    // ldmatrix lane addressing (canonical x4 fragment order)
    const int lr = (lane & 7) + ((lane >> 3) & 1) * 8;   // row within 16
    const int lk = (lane >> 4) * 16;                     // 16B col half

    float acc[4][8][4];
    #pragma unroll
    for (int mi = 0; mi < 4; mi++)
        #pragma unroll
        for (int j = 0; j < 8; j++)
            #pragma unroll
            for (int v = 0; v < 4; v++) acc[mi][j][v] = 0.f;

    int b3 = 0;                          // it % 3
    for (int it = 0; it < 8; ++it){
        if (it == 7) asm volatile("cp.async.wait_group 0;" ::: "memory");
        else         asm volatile("cp.async.wait_group 1;" ::: "memory");
        __syncthreads();                 // the ONLY barrier per iter

        // issue next-next B into the stage consumed at it-1 (safe post-sync)
        if (it + 2 < 8){
            int nb = b3 + 2; if (nb >= 3) nb -= 3;
            issueB(it + 2, bbuf[nb], tid);
        }
        // write A for it+1 into the A buffer consumed at it-1 (safe post-sync)
        if (it + 1 < 8){
            stsA(ab[(it+1)&1], rb, c16, pf, ss);
            if (it + 2 < 8){
                #pragma unroll
                for (int i = 0; i < 4; i++)
                    pf[i] = *reinterpret_cast<const float4*>(Ag + (size_t)i*16*DD + (it+2)*64);
            }
        }

        const uint32_t abase = ab[it & 1];
        const uint32_t bbase = bbuf[b3];
        #pragma unroll
        for (int ks = 0; ks < 4; ks++){
            uint32_t af[4][4];
            #pragma unroll
            for (int mi = 0; mi < 4; mi++){
                int r = mi*16 + lr;
                ldsm4(af[mi][0], af[mi][1], af[mi][2], af[mi][3],
                      abase + swz((uint32_t)(r*128 + ks*32 + lk)));
            }
            uint32_t bf[4][4];
            #pragma unroll
            for (int jj = 0; jj < 4; jj++){
                int r = nw*64 + jj*16 + lr;
                ldsm4(bf[jj][0], bf[jj][1], bf[jj][2], bf[jj][3],
                      bbase + swz((uint32_t)(r*128 + ks*32 + lk)));
            }
            #pragma unroll
            for (int mi = 0; mi < 4; mi++)
                #pragma unroll
                for (int j = 0; j < 8; j++)
                    mma16816(acc[mi][j], af[mi], bf[j>>1][j&1], bf[j>>1][(j&1)+2]);
        }
        b3++; if (b3 >= 3) b3 -= 3;
    }
    __syncthreads();                     // A/B stages dead; s_t overlay begins

    // patch norms: reduce sumsq over the 16-lane group sharing each row
    #pragma unroll
    for (int i = 0; i < 4; i++){
        float s = ss[i];
        s += __shfl_xor_sync(0xffffffffu, s, 1);
        s += __shfl_xor_sync(0xffffffffu, s, 2);
        s += __shfl_xor_sync(0xffffffffu, s, 4);
        s += __shfl_xor_sync(0xffffffffu, s, 8);
        if (c16 == 0) s_rnp[rb + 16*i] = 1.0f / fmaxf(sqrtf(s), 1e-12f);
    }
    __syncthreads();

    // ---- epilogue: scale, softmax over full 512 cols, normalized fp16 store
    float rs[4][2], rt[8][2];
    #pragma unroll
    for (int mi = 0; mi < 4; mi++)
        #pragma unroll
        for (int h = 0; h < 2; h++)
            rs[mi][h] = s_rnp[mi*16 + h*8 + gid] * INV_TEMP;
    #pragma unroll
    for (int j = 0; j < 8; j++){
        int c0 = nw*64 + j*8 + tig*2;
        rt[j][0] = s_rnt[c0]; rt[j][1] = s_rnt[c0+1];
    }
    #pragma unroll
    for (int mi = 0; mi < 4; mi++)
        #pragma unroll
        for (int j = 0; j < 8; j++)
            #pragma unroll
            for (int v = 0; v < 4; v++)
                acc[mi][j][v] *= rs[mi][v>>1] * rt[j][v&1];

    // per-row max (warp slice over its 64 cols), quad shuffle, 8-warp smem reduce
    #pragma unroll
    for (int mi = 0; mi < 4; mi++)
        #pragma unroll
        for (int h = 0; h < 2; h++){
            float mx = -3.0e38f;
            #pragma unroll
            for (int j = 0; j < 8; j++)
                mx = fmaxf(mx, fmaxf(acc[mi][j][2*h], acc[mi][j][2*h+1]));
            mx = fmaxf(mx, __shfl_xor_sync(0xffffffffu, mx, 1));
            mx = fmaxf(mx, __shfl_xor_sync(0xffffffffu, mx, 2));
            if (tig == 0) s_red[(mi*16 + h*8 + gid)*8 + nw] = mx;
        }
    __syncthreads();
    if (tid < 64){
        float m = s_red[tid*8];
        #pragma unroll
        for (int k = 1; k < 8; k++) m = fmaxf(m, s_red[tid*8 + k]);
        s_gmax[tid] = m;
    }
    __syncthreads();

    // exp + row sum
    #pragma unroll
    for (int mi = 0; mi < 4; mi++)
        #pragma unroll
        for (int h = 0; h < 2; h++){
            float gm = s_gmax[mi*16 + h*8 + gid];
            float sm = 0.f;
            #pragma unroll
            for (int j = 0; j < 8; j++){
                float e0 = __expf(acc[mi][j][2*h]   - gm);
                float e1 = __expf(acc[mi][j][2*h+1] - gm);
                acc[mi][j][2*h] = e0; acc[mi][j][2*h+1] = e1;
                sm += e0 + e1;
            }
            sm += __shfl_xor_sync(0xffffffffu, sm, 1);
            sm += __shfl_xor_sync(0xffffffffu, sm, 2);
            if (tig == 0) s_red[(mi*16 + h*8 + gid)*8 + nw] = sm;
        }
    __syncthreads();
    if (tid < 64){
        float s = 0.f;
        #pragma unroll
        for (int k = 0; k < 8; k++) s += s_red[tid*8 + k];
        s_rzv[tid] = 1.0f / s;
    }
    __syncthreads();

    // normalized transposed store into padded smem [c][n], stride 68
    #pragma unroll
    for (int mi = 0; mi < 4; mi++)
        #pragma unroll
        for (int j = 0; j < 8; j++)
            #pragma unroll
            for (int v = 0; v < 4; v++){
                int col = nw*64 + j*8 + tig*2 + (v&1);
                int row = mi*16 + (v>>1)*8 + gid;
                s_t[col*68 + row] = acc[mi][j][v] * s_rzv[row];
            }
    __syncthreads();

    // vectorized coalesced fp16 copy-out: g_aff[b][c][nt*64 + n]
    __half* obase = g_aff + (size_t)b * CC * NN + (size_t)nt * 64;
    const int cpart = tid >> 4;           // 0..15
    const int n4    = (tid & 15) * 4;     // 0..60
    #pragma unroll 4
    for (int itc = 0; itc < 32; itc++){
        int c = itc*16 + cpart;
        float4 f = *reinterpret_cast<const float4*>(&s_t[c*68 + n4]);
        union { __half2 h[2]; uint2 u; } U;
        U.h[0] = __floats2half2_rn(f.x, f.y);
        U.h[1] = __floats2half2_rn(f.z, f.w);
        *reinterpret_cast<uint2*>(obase + (size_t)c * NN + n4) = U.u;
    }
}

// ================= kernel 4: top-16, 2 interleaved chains per warp ===========
// key = (fp16bits << 16) | (lane << 3) | chunk : one redux gives value+owner+chunk
__global__ void topk_kernel(float* __restrict__ out){
    int w    = (blockIdx.x * blockDim.x + threadIdx.x) >> 5;  // pair index
    int lane = threadIdx.x & 31;
    if (w >= BB*CC/2) return;
    const int w0 = w*2;
    const uint4* pA = reinterpret_cast<const uint4*>(g_aff + (size_t)w0     * NN);
    const uint4* pB = reinterpret_cast<const uint4*>(g_aff + (size_t)(w0+1) * NN);

    unsigned vA[32], vB[32], ckA[8], ckB[8];
    #pragma unroll
    for (int j = 0; j < 4; j++){
        uint4 qa = pA[j*32 + lane];
        uint4 qb = pB[j*32 + lane];
        vA[8*j+0]=qa.x&0xFFFFu; vA[8*j+1]=qa.x>>16; vA[8*j+2]=qa.y&0xFFFFu; vA[8*j+3]=qa.y>>16;
        vA[8*j+4]=qa.z&0xFFFFu; vA[8*j+5]=qa.z>>16; vA[8*j+6]=qa.w&0xFFFFu; vA[8*j+7]=qa.w>>16;
        vB[8*j+0]=qb.x&0xFFFFu; vB[8*j+1]=qb.x>>16; vB[8*j+2]=qb.y&0xFFFFu; vB[8*j+3]=qb.y>>16;
        vB[8*j+4]=qb.z&0xFFFFu; vB[8*j+5]=qb.z>>16; vB[8*j+6]=qb.w&0xFFFFu; vB[8*j+7]=qb.w>>16;
    }
    #pragma unroll
    for (int c = 0; c < 8; c++){
        unsigned a0 = vA[4*c]   > vA[4*c+1] ? vA[4*c]   : vA[4*c+1];
        unsigned a1 = vA[4*c+2] > vA[4*c+3] ? vA[4*c+2] : vA[4*c+3];
        ckA[c] = (((a0 > a1 ? a0 : a1)) << 16) | ((unsigned)lane << 3) | (unsigned)c;
        unsigned b0 = vB[4*c]   > vB[4*c+1] ? vB[4*c]   : vB[4*c+1];
        unsigned b1 = vB[4*c+2] > vB[4*c+3] ? vB[4*c+2] : vB[4*c+3];
        ckB[c] = (((b0 > b1 ? b0 : b1)) << 16) | ((unsigned)lane << 3) | (unsigned)c;
    }
    unsigned lkA = ckA[0], lkB = ckB[0];
    #pragma unroll
    for (int c = 1; c < 8; c++){
        lkA = ckA[c] > lkA ? ckA[c] : lkA;
        lkB = ckB[c] > lkB ? ckB[c] : lkB;
    }

    float sumA = 0.f, sumB = 0.f;
    #pragma unroll
    for (int it = 0; it < KTOP; ++it){
        unsigned mA, mB;
        asm("redux.sync.max.u32 %0, %1, 0xffffffff;" : "=r"(mA) : "r"(lkA));
        asm("redux.sync.max.u32 %0, %1, 0xffffffff;" : "=r"(mB) : "r"(lkB));
        { __half_raw hr; hr.x = (unsigned short)(mA >> 16);
          sumA += __half2float(*reinterpret_cast<__half*>(&hr)); }
        { __half_raw hr; hr.x = (unsigned short)(mB >> 16);
          sumB += __half2float(*reinterpret_cast<__half*>(&hr)); }
        if (((mA >> 3) & 31u) == (unsigned)lane){
            unsigned val = mA >> 16; int oc = (int)(mA & 7u);
            #pragma unroll
            for (int c = 0; c < 8; c++) if (c == oc){
                if      (vA[4*c]   == val) vA[4*c]   = 0u;
                else if (vA[4*c+1] == val) vA[4*c+1] = 0u;
                else if (vA[4*c+2] == val) vA[4*c+2] = 0u;
                else                       vA[4*c+3] = 0u;
                unsigned a0 = vA[4*c]   > vA[4*c+1] ? vA[4*c]   : vA[4*c+1];
                unsigned a1 = vA[4*c+2] > vA[4*c+3] ? vA[4*c+2] : vA[4*c+3];
                ckA[c] = (((a0 > a1 ? a0 : a1)) << 16) | ((unsigned)lane << 3) | (unsigned)c;
            }
            lkA = ckA[0];
            #pragma unroll
            for (int c = 1; c < 8; c++) lkA = ckA[c] > lkA ? ckA[c] : lkA;
        }
        if (((mB >> 3) & 31u) == (unsigned)lane){
            unsigned val = mB >> 16; int oc = (int)(mB & 7u);
            #pragma unroll
            for (int c = 0; c < 8; c++) if (c == oc){
                if      (vB[4*c]   == val) vB[4*c]   = 0u;
                else if (vB[4*c+1] == val) vB[4*c+1] = 0u;
                else if (vB[4*c+2] == val) vB[4*c+2] = 0u;
                else                       vB[4*c+3] = 0u;
                unsigned b0 = vB[4*c]   > vB[4*c+1] ? vB[4*c]   : vB[4*c+1];
                unsigned b1 = vB[4*c+2] > vB[4*c+3] ? vB[4*c+2] : vB[4*c+3];
                ckB[c] = (((b0 > b1 ? b0 : b1)) << 16) | ((unsigned)lane << 3) | (unsigned)c;
            }
            lkB = ckB[0];
            #pragma unroll
            for (int c = 1; c < 8; c++) lkB = ckB[c] > lkB ? ckB[c] : lkB;
        }
    }
    if (lane == 0){
        out[w0]     += 0.7f * (sumA * (1.0f / (float)KTOP));
        out[w0 + 1] += 0.7f * (sumB * (1.0f / (float)KTOP));
    }
}

// ================= launch =====================================================
extern "C" void kernel_launch(void* const* d_in, const int* in_sizes, int n_in,
                              void* d_out, int out_size){
    const float* vcls = nullptr;
    const float* vp   = nullptr;
    const float* text = nullptr;
    for (int i = 0; i < n_in; i++){
        if      (in_sizes[i] == BB*DD)     vcls = (const float*)d_in[i];
        else if (in_sizes[i] == BB*NN*DD)  vp   = (const float*)d_in[i];
        else if (in_sizes[i] == CC*DD)     text = (const float*)d_in[i];
    }
    float* out = (float*)d_out;

    cudaFuncSetAttribute(gemm_softmax_kernel,
                         cudaFuncAttributeMaxDynamicSharedMemorySize, SM_DYN);

    const int nwarps = CC + BB;
    convert_kernel<<<(nwarps*32 + 255)/256, 256>>>(vcls, text);
    affg_kernel<<<BB, 512>>>(vcls, text, out);
    gemm_softmax_kernel<<<1024, 256, SM_DYN>>>(vp);
    topk_kernel<<<(BB*CC/2*32 + 255)/256, 256>>>(out);
}

// round 11
// speedup vs baseline: 1.3815x; 1.2218x over previous
#include <cuda_runtime.h>
#include <cuda_fp16.h>
#include <math.h>
#include <stdint.h>

#define BB 64
#define NN 1024
#define DD 512
#define CC 512
#define KTOP 16
#define INV_TEMP (1.0f/0.07f)

// ---------------- scratch (device globals: no allocations allowed) ----------
__device__ __half g_aff[(size_t)BB * CC * NN];    // [b][c][n] normalized softmax p (fp16)
__device__ float g_rnt[CC];
__device__ float g_rnc[BB];
__device__ __half g_txh[(size_t)CC*DD];           // text fp16

// ================= helpers ====================================================
static __device__ __forceinline__ uint32_t smem_u32(const void* p){
    uint32_t a;
    asm("{ .reg .u64 t; cvta.to.shared.u64 t, %1; cvt.u32.u64 %0, t; }" : "=r"(a) : "l"(p));
    return a;
}
static __device__ __forceinline__ void cpasync16(uint32_t dst, const void* src){
    asm volatile("cp.async.cg.shared.global [%0], [%1], 16;" :: "r"(dst), "l"(src) : "memory");
}
static __device__ __forceinline__ uint32_t swz(uint32_t o){ return o ^ ((o >> 3) & 0x70u); }

static __device__ __forceinline__ void ldsm4(uint32_t &r0, uint32_t &r1,
                                             uint32_t &r2, uint32_t &r3, uint32_t addr){
    asm volatile("ldmatrix.sync.aligned.m8n8.x4.shared.b16 {%0,%1,%2,%3}, [%4];"
        : "=r"(r0), "=r"(r1), "=r"(r2), "=r"(r3) : "r"(addr));
}
static __device__ __forceinline__ void mma16816(float* d, const uint32_t* a,
                                                uint32_t b0, uint32_t b1){
    asm volatile("mma.sync.aligned.m16n8k16.row.col.f32.f16.f16.f32 "
        "{%0,%1,%2,%3}, {%4,%5,%6,%7}, {%8,%9}, {%0,%1,%2,%3};"
        : "+f"(d[0]), "+f"(d[1]), "+f"(d[2]), "+f"(d[3])
        : "r"(a[0]), "r"(a[1]), "r"(a[2]), "r"(a[3]), "r"(b0), "r"(b1));
}

// ================= kernel 1: text fp16 convert + text/cls L2 norms ===========
__global__ void convert_kernel(const float* __restrict__ vcls,
                               const float* __restrict__ text){
    int w    = (blockIdx.x * blockDim.x + threadIdx.x) >> 5;
    int lane = threadIdx.x & 31;
    const int NW = CC + BB;
    if (w >= NW) return;
    const float* src; __half* hi = nullptr; float* rdst;
    if (w < CC){ src = text + (size_t)w*DD; hi = g_txh + (size_t)w*DD; rdst = g_rnt + w; }
    else       { int ci = w - CC; src = vcls + (size_t)ci*DD; rdst = g_rnc + ci; }
    float ss = 0.f;
    #pragma unroll
    for (int j = 0; j < 4; j++){
        int o = (j*32 + lane) * 4;
        float4 v = *reinterpret_cast<const float4*>(src + o);
        ss += v.x*v.x + v.y*v.y + v.z*v.z + v.w*v.w;
        if (hi){
            union { __half2 h2[2]; uint2 u; } P;
            P.h2[0] = __floats2half2_rn(v.x, v.y);
            P.h2[1] = __floats2half2_rn(v.z, v.w);
            *reinterpret_cast<uint2*>(hi + o) = P.u;
        }
    }
    #pragma unroll
    for (int off = 16; off; off >>= 1) ss += __shfl_xor_sync(0xffffffffu, ss, off);
    if (lane == 0) *rdst = 1.0f / fmaxf(sqrtf(ss), 1e-12f);
}

// ================= kernel 2: global affinity, writes 0.3*softmax ============
__global__ __launch_bounds__(512) void affg_kernel(const float* __restrict__ vcls,
                                                   const float* __restrict__ text,
                                                   float* __restrict__ out){
    __shared__ float sv[DD];
    __shared__ float red[16];
    int b = blockIdx.x, tid = threadIdx.x;
    sv[tid] = vcls[b*DD + tid];
    __syncthreads();
    const float* t = text + (size_t)tid * DD;
    float dot = 0.f;
    #pragma unroll 4
    for (int k = 0; k < DD; k += 4){
        float4 v = *reinterpret_cast<const float4*>(t + k);
        dot += v.x*sv[k] + v.y*sv[k+1] + v.z*sv[k+2] + v.w*sv[k+3];
    }
    float logit = dot * g_rnc[b] * g_rnt[tid] * INV_TEMP;
    int lane = tid & 31, wid = tid >> 5;
    float m = logit;
    #pragma unroll
    for (int off = 16; off; off >>= 1) m = fmaxf(m, __shfl_xor_sync(0xffffffffu, m, off));
    if (lane == 0) red[wid] = m;
    __syncthreads();
    float bm = red[0];
    #pragma unroll
    for (int i = 1; i < 16; i++) bm = fmaxf(bm, red[i]);
    __syncthreads();
    float e = __expf(logit - bm);
    float s = e;
    #pragma unroll
    for (int off = 16; off; off >>= 1) s += __shfl_xor_sync(0xffffffffu, s, off);
    if (lane == 0) red[wid] = s;
    __syncthreads();
    float bs = 0.f;
    #pragma unroll
    for (int i = 0; i < 16; i++) bs += red[i];
    out[b*CC + tid] = 0.3f * e / bs;
}

// ================= kernel 3: fp16 HMMA GEMM, 16 warps, fused A ==============
// CTA: 64 patches x 512 classes, 512 threads (16 warps: mw=wid>>3, nw=wid&7).
// Warp tile 32x64 (acc 64 regs). kc=64, 8 k-iters, 2-stage pipeline (r8-style).
#define SM_A0   0u
#define SM_A1   8192u
#define SM_B0   16384u
#define SM_B1   81920u
#define SM_AUX  147456u
#define SM_DYN  (152576u + 1024u)

static __device__ __forceinline__ void issueB(int kt, uint32_t b_dst, int tid){
    const __half* Bb = g_txh + kt * 64;
    #pragma unroll
    for (int t = 0; t < 8; t++){   // B: 512 rows x 128B = 4096 chunks / 512 thr
        int g = tid + t*512; int row = g >> 3; int c = g & 7;
        cpasync16(b_dst + swz(row*128 + c*16), Bb + (size_t)row*DD + c*8);
    }
    asm volatile("cp.async.commit_group;" ::: "memory");
}

// convert & store 2 rows' chunks of A (rows rw, rw+32; 16B chunk c16), sumsq
static __device__ __forceinline__ void stsA(uint32_t abase, int rw, int c16,
                                            const float4* pf, float* ss){
    #pragma unroll
    for (int i = 0; i < 2; i++){
        union { __half2 h2; uint32_t u; } P0, P1;
        P0.h2 = __floats2half2_rn(pf[i].x, pf[i].y);
        P1.h2 = __floats2half2_rn(pf[i].z, pf[i].w);
        ss[i] += pf[i].x*pf[i].x + pf[i].y*pf[i].y + pf[i].z*pf[i].z + pf[i].w*pf[i].w;
        uint32_t off = (uint32_t)((rw + 32*i)*128 + c16*8);
        asm volatile("st.shared.v2.b32 [%0], {%1,%2};"
            :: "r"(abase + swz(off)), "r"(P0.u), "r"(P1.u) : "memory");
    }
}

__global__ __launch_bounds__(512, 1) void gemm_softmax_kernel(const float* __restrict__ vp){
    extern __shared__ __align__(16) char dsm[];
    const uint32_t raw  = smem_u32(dsm);
    const uint32_t base = (raw + 1023u) & ~1023u;
    char* bp = dsm + (base - raw);

    const int tid = threadIdx.x;
    const int pb  = blockIdx.x;          // 0..1023
    const int b   = pb >> 4;
    const int nt  = pb & 15;

    const uint32_t ab[2]   = { base + SM_A0, base + SM_A1 };
    const uint32_t bbuf[2] = { base + SM_B0, base + SM_B1 };
    float* s_t    = reinterpret_cast<float*>(bp);                    // 512*68 f (overlays stages)
    float* s_rnt  = reinterpret_cast<float*>(bp + SM_AUX);           // 512 f
    float* s_rnp  = reinterpret_cast<float*>(bp + SM_AUX + 2048);    // 64 f
    float* s_red  = reinterpret_cast<float*>(bp + SM_AUX + 2304);    // 64*8 f
    float* s_gmax = reinterpret_cast<float*>(bp + SM_AUX + 4352);    // 64 f
    float* s_rzv  = reinterpret_cast<float*>(bp + SM_AUX + 4608);    // 64 f

    const int wid  = tid >> 5;
    const int lane = tid & 31;
    const int mw   = wid >> 3;           // 0..1
    const int nw   = wid & 7;            // 0..7
    const int gid  = lane >> 2;          // row group 0..7
    const int tig  = lane & 3;

    if (tid < 512) s_rnt[tid] = g_rnt[tid];

    // fused A path: 1024 float4 chunks per k-tile, 2 per thread (rows rw, rw+32)
    const int c16 = tid & 15;            // 16B chunk within 64-float slab row
    const int rw  = tid >> 4;            // row 0..31; second row = rw+32
    const float* Ag = vp + ((size_t)(pb*64 + rw))*DD + c16*4;

    float4 pf[2];
    pf[0] = *reinterpret_cast<const float4*>(Ag);
    pf[1] = *reinterpret_cast<const float4*>(Ag + (size_t)32*DD);

    issueB(0, bbuf[0], tid);
    issueB(1, bbuf[1], tid);

    float ss[2] = {0.f, 0.f};
    stsA(ab[0], rw, c16, pf, ss);                        // A tile for kt=0
    pf[0] = *reinterpret_cast<const float4*>(Ag + 64);
    pf[1] = *reinterpret_cast<const float4*>(Ag + (size_t)32*DD + 64);

    // ldmatrix lane addressing (canonical x4 fragment order)
    const int lr = (lane & 7) + ((lane >> 3) & 1) * 8;   // row within 16
    const int lk = (lane >> 4) * 16;                     // 16B col half

    float acc[2][8][4];
    #pragma unroll
    for (int mi = 0; mi < 2; mi++)
        #pragma unroll
        for (int j = 0; j < 8; j++)
            #pragma unroll
            for (int v = 0; v < 4; v++) acc[mi][j][v] = 0.f;

    for (int it = 0; it < 8; ++it){
        const int cur = it & 1;
        if (it == 7) asm volatile("cp.async.wait_group 0;" ::: "memory");
        else         asm volatile("cp.async.wait_group 1;" ::: "memory");
        __syncthreads();

        const uint32_t abase = ab[cur];
        const uint32_t bbase = bbuf[cur];
        #pragma unroll
        for (int ks = 0; ks < 4; ks++){
            uint32_t af[2][4];
            #pragma unroll
            for (int mi = 0; mi < 2; mi++){
                int r = mw*32 + mi*16 + lr;
                ldsm4(af[mi][0], af[mi][1], af[mi][2], af[mi][3],
                      abase + swz((uint32_t)(r*128 + ks*32 + lk)));
            }
            uint32_t bf[4][4];
            #pragma unroll
            for (int jj = 0; jj < 4; jj++){
                int r = nw*64 + jj*16 + lr;
                ldsm4(bf[jj][0], bf[jj][1], bf[jj][2], bf[jj][3],
                      bbase + swz((uint32_t)(r*128 + ks*32 + lk)));
            }
            #pragma unroll
            for (int mi = 0; mi < 2; mi++)
                #pragma unroll
                for (int j = 0; j < 8; j++)
                    mma16816(acc[mi][j], af[mi], bf[j>>1][j&1], bf[j>>1][(j&1)+2]);
        }
        __syncthreads();
        if (it + 1 < 8) stsA(ab[(it+1)&1], rw, c16, pf, ss);   // A tile for kt=it+1
        if (it + 2 < 8){
            pf[0] = *reinterpret_cast<const float4*>(Ag + (it+2)*64);
            pf[1] = *reinterpret_cast<const float4*>(Ag + (size_t)32*DD + (it+2)*64);
            issueB(it + 2, bbuf[cur], tid);
        }
    }

    // patch norms: reduce sumsq over the 16-lane group sharing each row
    #pragma unroll
    for (int i = 0; i < 2; i++){
        float s = ss[i];
        s += __shfl_xor_sync(0xffffffffu, s, 1);
        s += __shfl_xor_sync(0xffffffffu, s, 2);
        s += __shfl_xor_sync(0xffffffffu, s, 4);
        s += __shfl_xor_sync(0xffffffffu, s, 8);
        if (c16 == 0) s_rnp[rw + 32*i] = 1.0f / fmaxf(sqrtf(s), 1e-12f);
    }
    __syncthreads();

    // ---- epilogue: scale, softmax over full 512 cols, normalized fp16 store
    float rs[2][2], rt[8][2];
    #pragma unroll
    for (int mi = 0; mi < 2; mi++)
        #pragma unroll
        for (int h = 0; h < 2; h++)
            rs[mi][h] = s_rnp[mw*32 + mi*16 + h*8 + gid] * INV_TEMP;
    #pragma unroll
    for (int j = 0; j < 8; j++){
        int c0 = nw*64 + j*8 + tig*2;
        rt[j][0] = s_rnt[c0]; rt[j][1] = s_rnt[c0+1];
    }
    #pragma unroll
    for (int mi = 0; mi < 2; mi++)
        #pragma unroll
        for (int j = 0; j < 8; j++)
            #pragma unroll
            for (int v = 0; v < 4; v++)
                acc[mi][j][v] *= rs[mi][v>>1] * rt[j][v&1];

    // per-row max (warp slice over its 64 cols), quad shuffle, 8-warp smem reduce
    #pragma unroll
    for (int mi = 0; mi < 2; mi++)
        #pragma unroll
        for (int h = 0; h < 2; h++){
            float mx = -3.0e38f;
            #pragma unroll
            for (int j = 0; j < 8; j++)
                mx = fmaxf(mx, fmaxf(acc[mi][j][2*h], acc[mi][j][2*h+1]));
            mx = fmaxf(mx, __shfl_xor_sync(0xffffffffu, mx, 1));
            mx = fmaxf(mx, __shfl_xor_sync(0xffffffffu, mx, 2));
            if (tig == 0) s_red[(mw*32 + mi*16 + h*8 + gid)*8 + nw] = mx;
        }
    __syncthreads();
    if (tid < 64){
        float m = s_red[tid*8];
        #pragma unroll
        for (int k = 1; k < 8; k++) m = fmaxf(m, s_red[tid*8 + k]);
        s_gmax[tid] = m;
    }
    __syncthreads();

    // exp + row sum
    #pragma unroll
    for (int mi = 0; mi < 2; mi++)
        #pragma unroll
        for (int h = 0; h < 2; h++){
            float gm = s_gmax[mw*32 + mi*16 + h*8 + gid];
            float sm = 0.f;
            #pragma unroll
            for (int j = 0; j < 8; j++){
                float e0 = __expf(acc[mi][j][2*h]   - gm);
                float e1 = __expf(acc[mi][j][2*h+1] - gm);
                acc[mi][j][2*h] = e0; acc[mi][j][2*h+1] = e1;
                sm += e0 + e1;
            }
            sm += __shfl_xor_sync(0xffffffffu, sm, 1);
            sm += __shfl_xor_sync(0xffffffffu, sm, 2);
            if (tig == 0) s_red[(mw*32 + mi*16 + h*8 + gid)*8 + nw] = sm;
        }
    __syncthreads();
    if (tid < 64){
        float s = 0.f;
        #pragma unroll
        for (int k = 0; k < 8; k++) s += s_red[tid*8 + k];
        s_rzv[tid] = 1.0f / s;
    }
    __syncthreads();

    // normalized transposed store into padded smem [c][n], stride 68
    #pragma unroll
    for (int mi = 0; mi < 2; mi++)
        #pragma unroll
        for (int j = 0; j < 8; j++)
            #pragma unroll
            for (int v = 0; v < 4; v++){
                int col = nw*64 + j*8 + tig*2 + (v&1);
                int row = mw*32 + mi*16 + (v>>1)*8 + gid;
                s_t[col*68 + row] = acc[mi][j][v] * s_rzv[row];
            }
    __syncthreads();

    // vectorized coalesced fp16 copy-out: g_aff[b][c][nt*64 + n]
    __half* obase = g_aff + (size_t)b * CC * NN + (size_t)nt * 64;
    const int cpart = tid >> 4;           // 0..31
    const int n4    = (tid & 15) * 4;     // 0..60
    #pragma unroll 4
    for (int itc = 0; itc < 16; itc++){
        int c = itc*32 + cpart;
        float4 f = *reinterpret_cast<const float4*>(&s_t[c*68 + n4]);
        union { __half2 h[2]; uint2 u; } U;
        U.h[0] = __floats2half2_rn(f.x, f.y);
        U.h[1] = __floats2half2_rn(f.z, f.w);
        *reinterpret_cast<uint2*>(obase + (size_t)c * NN + n4) = U.u;
    }
}

// ================= kernel 4: top-16 over N per (b,c), blend ==================
// key = (fp16bits << 16) | (lane << 3) | chunk : one redux gives value+owner+chunk
__global__ void topk_kernel(float* __restrict__ out){
    int w    = (blockIdx.x * blockDim.x + threadIdx.x) >> 5;  // b*512 + c
    int lane = threadIdx.x & 31;
    if (w >= BB*CC) return;
    const uint4* p = reinterpret_cast<const uint4*>(g_aff + (size_t)w * NN);

    unsigned v[32], ck[8];
    #pragma unroll
    for (int j = 0; j < 4; j++){
        uint4 q = p[j*32 + lane];
        v[8*j+0] = q.x & 0xFFFFu; v[8*j+1] = q.x >> 16;
        v[8*j+2] = q.y & 0xFFFFu; v[8*j+3] = q.y >> 16;
        v[8*j+4] = q.z & 0xFFFFu; v[8*j+5] = q.z >> 16;
        v[8*j+6] = q.w & 0xFFFFu; v[8*j+7] = q.w >> 16;
    }
    #pragma unroll
    for (int c = 0; c < 8; c++){
        unsigned m0 = v[4*c]   > v[4*c+1] ? v[4*c]   : v[4*c+1];
        unsigned m1 = v[4*c+2] > v[4*c+3] ? v[4*c+2] : v[4*c+3];
        unsigned mv = m0 > m1 ? m0 : m1;
        ck[c] = (mv << 16) | ((unsigned)lane << 3) | (unsigned)c;
    }
    unsigned lk = ck[0];
    #pragma unroll
    for (int c = 1; c < 8; c++) lk = ck[c] > lk ? ck[c] : lk;

    float sum = 0.f;
    #pragma unroll
    for (int it = 0; it < KTOP; ++it){
        unsigned m;
        asm("redux.sync.max.u32 %0, %1, 0xffffffff;" : "=r"(m) : "r"(lk));
        __half_raw hr; hr.x = (unsigned short)(m >> 16);
        sum += __half2float(*reinterpret_cast<__half*>(&hr));
        if (((m >> 3) & 31u) == (unsigned)lane){
            unsigned val = m >> 16;
            int oc = (int)(m & 7u);
            #pragma unroll
            for (int c = 0; c < 8; c++) if (c == oc){
                if      (v[4*c]   == val) v[4*c]   = 0u;
                else if (v[4*c+1] == val) v[4*c+1] = 0u;
                else if (v[4*c+2] == val) v[4*c+2] = 0u;
                else                      v[4*c+3] = 0u;
                unsigned m0 = v[4*c]   > v[4*c+1] ? v[4*c]   : v[4*c+1];
                unsigned m1 = v[4*c+2] > v[4*c+3] ? v[4*c+2] : v[4*c+3];
                unsigned mv = m0 > m1 ? m0 : m1;
                ck[c] = (mv << 16) | ((unsigned)lane << 3) | (unsigned)c;
            }
            lk = ck[0];
            #pragma unroll
            for (int c = 1; c < 8; c++) lk = ck[c] > lk ? ck[c] : lk;
        }
    }
    if (lane == 0) out[w] += 0.7f * (sum * (1.0f / (float)KTOP));
}

// ================= launch =====================================================
extern "C" void kernel_launch(void* const* d_in, const int* in_sizes, int n_in,
                              void* d_out, int out_size){
    const float* vcls = nullptr;
    const float* vp   = nullptr;
    const float* text = nullptr;
    for (int i = 0; i < n_in; i++){
        if      (in_sizes[i] == BB*DD)     vcls = (const float*)d_in[i];
        else if (in_sizes[i] == BB*NN*DD)  vp   = (const float*)d_in[i];
        else if (in_sizes[i] == CC*DD)     text = (const float*)d_in[i];
    }
    float* out = (float*)d_out;

    cudaFuncSetAttribute(gemm_softmax_kernel,
                         cudaFuncAttributeMaxDynamicSharedMemorySize, SM_DYN);

    const int nwarps = CC + BB;
    convert_kernel<<<(nwarps*32 + 255)/256, 256>>>(vcls, text);
    affg_kernel<<<BB, 512>>>(vcls, text, out);
    gemm_softmax_kernel<<<1024, 512, SM_DYN>>>(vp);
    topk_kernel<<<(BB*CC*32 + 255)/256, 256>>>(out);
}

// round 12
// speedup vs baseline: 1.4470x; 1.0474x over previous
#include <cuda_runtime.h>
#include <cuda_fp16.h>
#include <math.h>
#include <stdint.h>

#define BB 64
#define NN 1024
#define DD 512
#define CC 512
#define KTOP 16
#define INV_TEMP (1.0f/0.07f)

// ---------------- scratch (device globals: no allocations allowed) ----------
__device__ __half g_aff[(size_t)BB * CC * NN];    // [b][c][n] normalized softmax p (fp16)
__device__ float g_rnt[CC];
__device__ float g_rnc[BB];
__device__ __half g_txh[(size_t)CC*DD];           // text fp16

// ================= helpers ====================================================
static __device__ __forceinline__ uint32_t smem_u32(const void* p){
    uint32_t a;
    asm("{ .reg .u64 t; cvta.to.shared.u64 t, %1; cvt.u32.u64 %0, t; }" : "=r"(a) : "l"(p));
    return a;
}
static __device__ __forceinline__ void cpasync16(uint32_t dst, const void* src){
    asm volatile("cp.async.cg.shared.global [%0], [%1], 16;" :: "r"(dst), "l"(src) : "memory");
}
static __device__ __forceinline__ uint32_t swz(uint32_t o){ return o ^ ((o >> 3) & 0x70u); }

static __device__ __forceinline__ void ldsm4(uint32_t &r0, uint32_t &r1,
                                             uint32_t &r2, uint32_t &r3, uint32_t addr){
    asm volatile("ldmatrix.sync.aligned.m8n8.x4.shared.b16 {%0,%1,%2,%3}, [%4];"
        : "=r"(r0), "=r"(r1), "=r"(r2), "=r"(r3) : "r"(addr));
}
static __device__ __forceinline__ void mma16816(float* d, const uint32_t* a,
                                                uint32_t b0, uint32_t b1){
    asm volatile("mma.sync.aligned.m16n8k16.row.col.f32.f16.f16.f32 "
        "{%0,%1,%2,%3}, {%4,%5,%6,%7}, {%8,%9}, {%0,%1,%2,%3};"
        : "+f"(d[0]), "+f"(d[1]), "+f"(d[2]), "+f"(d[3])
        : "r"(a[0]), "r"(a[1]), "r"(a[2]), "r"(a[3]), "r"(b0), "r"(b1));
}

// ================= kernel 1: text fp16 convert + text/cls L2 norms ===========
__global__ void convert_kernel(const float* __restrict__ vcls,
                               const float* __restrict__ text){
    int w    = (blockIdx.x * blockDim.x + threadIdx.x) >> 5;
    int lane = threadIdx.x & 31;
    const int NW = CC + BB;
    if (w >= NW) return;
    const float* src; __half* hi = nullptr; float* rdst;
    if (w < CC){ src = text + (size_t)w*DD; hi = g_txh + (size_t)w*DD; rdst = g_rnt + w; }
    else       { int ci = w - CC; src = vcls + (size_t)ci*DD; rdst = g_rnc + ci; }
    float ss = 0.f;
    #pragma unroll
    for (int j = 0; j < 4; j++){
        int o = (j*32 + lane) * 4;
        float4 v = *reinterpret_cast<const float4*>(src + o);
        ss += v.x*v.x + v.y*v.y + v.z*v.z + v.w*v.w;
        if (hi){
            union { __half2 h2[2]; uint2 u; } P;
            P.h2[0] = __floats2half2_rn(v.x, v.y);
            P.h2[1] = __floats2half2_rn(v.z, v.w);
            *reinterpret_cast<uint2*>(hi + o) = P.u;
        }
    }
    #pragma unroll
    for (int off = 16; off; off >>= 1) ss += __shfl_xor_sync(0xffffffffu, ss, off);
    if (lane == 0) *rdst = 1.0f / fmaxf(sqrtf(ss), 1e-12f);
}

// ================= kernel 2: global affinity, writes 0.3*softmax ============
// text read as fp16 (g_txh) — runs after convert_kernel.
__global__ __launch_bounds__(512) void affg_kernel(const float* __restrict__ vcls,
                                                   float* __restrict__ out){
    __shared__ float sv[DD];
    __shared__ float red[16];
    int b = blockIdx.x, tid = threadIdx.x;
    sv[tid] = vcls[b*DD + tid];
    __syncthreads();
    const uint4* t4 = reinterpret_cast<const uint4*>(g_txh + (size_t)tid * DD);
    float dot = 0.f;
    #pragma unroll 8
    for (int k = 0; k < 64; k++){
        uint4 q = t4[k];
        float2 f0 = __half22float2(*reinterpret_cast<__half2*>(&q.x));
        float2 f1 = __half22float2(*reinterpret_cast<__half2*>(&q.y));
        float2 f2 = __half22float2(*reinterpret_cast<__half2*>(&q.z));
        float2 f3 = __half22float2(*reinterpret_cast<__half2*>(&q.w));
        const float* s = &sv[k*8];
        dot += f0.x*s[0] + f0.y*s[1] + f1.x*s[2] + f1.y*s[3]
             + f2.x*s[4] + f2.y*s[5] + f3.x*s[6] + f3.y*s[7];
    }
    float logit = dot * g_rnc[b] * g_rnt[tid] * INV_TEMP;
    int lane = tid & 31, wid = tid >> 5;
    float m = logit;
    #pragma unroll
    for (int off = 16; off; off >>= 1) m = fmaxf(m, __shfl_xor_sync(0xffffffffu, m, off));
    if (lane == 0) red[wid] = m;
    __syncthreads();
    float bm = red[0];
    #pragma unroll
    for (int i = 1; i < 16; i++) bm = fmaxf(bm, red[i]);
    __syncthreads();
    float e = __expf(logit - bm);
    float s = e;
    #pragma unroll
    for (int off = 16; off; off >>= 1) s += __shfl_xor_sync(0xffffffffu, s, off);
    if (lane == 0) red[wid] = s;
    __syncthreads();
    float bs = 0.f;
    #pragma unroll
    for (int i = 0; i < 16; i++) bs += red[i];
    out[b*CC + tid] = 0.3f * e / bs;
}

// ================= kernel 3: fp16 HMMA GEMM, 16 warps, fused A ==============
// CTA: 64 patches x 512 classes, 512 threads (16 warps: mw=wid>>3, nw=wid&7).
// Warp tile 32x64. kc=64, 8 k-iters. B triple-buffered, A double-buffered,
// head-barrier-only pipeline (loads issued AFTER the MMA region, no tail sync).
#define SM_A0   0u
#define SM_A1   8192u
#define SM_B0   16384u
#define SM_B1   81920u
#define SM_B2   147456u
#define SM_AUX  212992u
#define SM_DYN  (212992u + 4864u + 1024u)

static __device__ __forceinline__ void issueB(int kt, uint32_t b_dst, int tid){
    const __half* Bb = g_txh + kt * 64;
    #pragma unroll
    for (int t = 0; t < 8; t++){   // B: 512 rows x 128B = 4096 chunks / 512 thr
        int g = tid + t*512; int row = g >> 3; int c = g & 7;
        cpasync16(b_dst + swz(row*128 + c*16), Bb + (size_t)row*DD + c*8);
    }
    asm volatile("cp.async.commit_group;" ::: "memory");
}

// convert & store 2 rows' chunks of A (rows rw, rw+32; 16B chunk c16), sumsq
static __device__ __forceinline__ void stsA(uint32_t abase, int rw, int c16,
                                            const float4* pf, float* ss){
    #pragma unroll
    for (int i = 0; i < 2; i++){
        union { __half2 h2; uint32_t u; } P0, P1;
        P0.h2 = __floats2half2_rn(pf[i].x, pf[i].y);
        P1.h2 = __floats2half2_rn(pf[i].z, pf[i].w);
        ss[i] += pf[i].x*pf[i].x + pf[i].y*pf[i].y + pf[i].z*pf[i].z + pf[i].w*pf[i].w;
        uint32_t off = (uint32_t)((rw + 32*i)*128 + c16*8);
        asm volatile("st.shared.v2.b32 [%0], {%1,%2};"
            :: "r"(abase + swz(off)), "r"(P0.u), "r"(P1.u) : "memory");
    }
}

__global__ __launch_bounds__(512, 1) void gemm_softmax_kernel(const float* __restrict__ vp){
    extern __shared__ __align__(16) char dsm[];
    const uint32_t raw  = smem_u32(dsm);
    const uint32_t base = (raw + 1023u) & ~1023u;
    char* bp = dsm + (base - raw);

    const int tid = threadIdx.x;
    const int pb  = blockIdx.x;          // 0..1023
    const int b   = pb >> 4;
    const int nt  = pb & 15;

    const uint32_t ab[2]   = { base + SM_A0, base + SM_A1 };
    const uint32_t bbuf[3] = { base + SM_B0, base + SM_B1, base + SM_B2 };
    float* s_t    = reinterpret_cast<float*>(bp);                    // 512*68 f (overlays stages)
    float* s_rnt  = reinterpret_cast<float*>(bp + SM_AUX);           // 512 f
    float* s_rnp  = reinterpret_cast<float*>(bp + SM_AUX + 2048);    // 64 f
    float* s_red  = reinterpret_cast<float*>(bp + SM_AUX + 2304);    // 64*8 f
    float* s_gmax = reinterpret_cast<float*>(bp + SM_AUX + 4352);    // 64 f
    float* s_rzv  = reinterpret_cast<float*>(bp + SM_AUX + 4608);    // 64 f

    const int wid  = tid >> 5;
    const int lane = tid & 31;
    const int mw   = wid >> 3;           // 0..1
    const int nw   = wid & 7;            // 0..7
    const int gid  = lane >> 2;          // row group 0..7
    const int tig  = lane & 3;

    if (tid < 512) s_rnt[tid] = g_rnt[tid];

    // fused A path: 1024 float4 chunks per k-tile, 2 per thread (rows rw, rw+32)
    const int c16 = tid & 15;            // 16B chunk within 64-float slab row
    const int rw  = tid >> 4;            // row 0..31; second row = rw+32
    const float* Ag = vp + ((size_t)(pb*64 + rw))*DD + c16*4;

    float4 pf[2];
    pf[0] = *reinterpret_cast<const float4*>(Ag);
    pf[1] = *reinterpret_cast<const float4*>(Ag + (size_t)32*DD);

    issueB(0, bbuf[0], tid);
    issueB(1, bbuf[1], tid);

    float ss[2] = {0.f, 0.f};
    stsA(ab[0], rw, c16, pf, ss);                        // A tile for kt=0
    pf[0] = *reinterpret_cast<const float4*>(Ag + 64);
    pf[1] = *reinterpret_cast<const float4*>(Ag + (size_t)32*DD + 64);

    // ldmatrix lane addressing (canonical x4 fragment order)
    const int lr = (lane & 7) + ((lane >> 3) & 1) * 8;   // row within 16
    const int lk = (lane >> 4) * 16;                     // 16B col half

    float acc[2][8][4];
    #pragma unroll
    for (int mi = 0; mi < 2; mi++)
        #pragma unroll
        for (int j = 0; j < 8; j++)
            #pragma unroll
            for (int v = 0; v < 4; v++) acc[mi][j][v] = 0.f;

    int b3 = 0;                          // it % 3
    for (int it = 0; it < 8; ++it){
        if (it == 7) asm volatile("cp.async.wait_group 0;" ::: "memory");
        else         asm volatile("cp.async.wait_group 1;" ::: "memory");
        __syncthreads();                 // head barrier (the only one per iter)

        const uint32_t abase = ab[it & 1];
        const uint32_t bbase = bbuf[b3];
        #pragma unroll
        for (int ks = 0; ks < 4; ks++){
            uint32_t af[2][4];
            #pragma unroll
            for (int mi = 0; mi < 2; mi++){
                int r = mw*32 + mi*16 + lr;
                ldsm4(af[mi][0], af[mi][1], af[mi][2], af[mi][3],
                      abase + swz((uint32_t)(r*128 + ks*32 + lk)));
            }
            uint32_t bf[4][4];
            #pragma unroll
            for (int jj = 0; jj < 4; jj++){
                int r = nw*64 + jj*16 + lr;
                ldsm4(bf[jj][0], bf[jj][1], bf[jj][2], bf[jj][3],
                      bbase + swz((uint32_t)(r*128 + ks*32 + lk)));
            }
            #pragma unroll
            for (int mi = 0; mi < 2; mi++)
                #pragma unroll
                for (int j = 0; j < 8; j++)
                    mma16816(acc[mi][j], af[mi], bf[j>>1][j&1], bf[j>>1][(j&1)+2]);
        }
        // post-MMA, no tail barrier: write A for it+1 (buffer consumed at it-1),
        // issue B for it+2 into stage consumed at it-1 — both safe past head sync.
        if (it + 1 < 8) stsA(ab[(it+1)&1], rw, c16, pf, ss);
        if (it + 2 < 8){
            pf[0] = *reinterpret_cast<const float4*>(Ag + (it+2)*64);
            pf[1] = *reinterpret_cast<const float4*>(Ag + (size_t)32*DD + (it+2)*64);
            int nb = b3 + 2; if (nb >= 3) nb -= 3;
            issueB(it + 2, bbuf[nb], tid);
        }
        b3++; if (b3 >= 3) b3 -= 3;
    }
    __syncthreads();                     // stages dead; s_t overlay begins

    // patch norms: reduce sumsq over the 16-lane group sharing each row
    #pragma unroll
    for (int i = 0; i < 2; i++){
        float s = ss[i];
        s += __shfl_xor_sync(0xffffffffu, s, 1);
        s += __shfl_xor_sync(0xffffffffu, s, 2);
        s += __shfl_xor_sync(0xffffffffu, s, 4);
        s += __shfl_xor_sync(0xffffffffu, s, 8);
        if (c16 == 0) s_rnp[rw + 32*i] = 1.0f / fmaxf(sqrtf(s), 1e-12f);
    }
    __syncthreads();

    // ---- epilogue: scale, softmax over full 512 cols, normalized fp16 store
    float rs[2][2], rt[8][2];
    #pragma unroll
    for (int mi = 0; mi < 2; mi++)
        #pragma unroll
        for (int h = 0; h < 2; h++)
            rs[mi][h] = s_rnp[mw*32 + mi*16 + h*8 + gid] * INV_TEMP;
    #pragma unroll
    for (int j = 0; j < 8; j++){
        int c0 = nw*64 + j*8 + tig*2;
        rt[j][0] = s_rnt[c0]; rt[j][1] = s_rnt[c0+1];
    }
    #pragma unroll
    for (int mi = 0; mi < 2; mi++)
        #pragma unroll
        for (int j = 0; j < 8; j++)
            #pragma unroll
            for (int v = 0; v < 4; v++)
                acc[mi][j][v] *= rs[mi][v>>1] * rt[j][v&1];

    // per-row max (warp slice over its 64 cols), quad shuffle, 8-warp smem reduce
    #pragma unroll
    for (int mi = 0; mi < 2; mi++)
        #pragma unroll
        for (int h = 0; h < 2; h++){
            float mx = -3.0e38f;
            #pragma unroll
            for (int j = 0; j < 8; j++)
                mx = fmaxf(mx, fmaxf(acc[mi][j][2*h], acc[mi][j][2*h+1]));
            mx = fmaxf(mx, __shfl_xor_sync(0xffffffffu, mx, 1));
            mx = fmaxf(mx, __shfl_xor_sync(0xffffffffu, mx, 2));
            if (tig == 0) s_red[(mw*32 + mi*16 + h*8 + gid)*8 + nw] = mx;
        }
    __syncthreads();
    if (tid < 64){
        float m = s_red[tid*8];
        #pragma unroll
        for (int k = 1; k < 8; k++) m = fmaxf(m, s_red[tid*8 + k]);
        s_gmax[tid] = m;
    }
    __syncthreads();

    // exp + row sum
    #pragma unroll
    for (int mi = 0; mi < 2; mi++)
        #pragma unroll
        for (int h = 0; h < 2; h++){
            float gm = s_gmax[mw*32 + mi*16 + h*8 + gid];
            float sm = 0.f;
            #pragma unroll
            for (int j = 0; j < 8; j++){
                float e0 = __expf(acc[mi][j][2*h]   - gm);
                float e1 = __expf(acc[mi][j][2*h+1] - gm);
                acc[mi][j][2*h] = e0; acc[mi][j][2*h+1] = e1;
                sm += e0 + e1;
            }
            sm += __shfl_xor_sync(0xffffffffu, sm, 1);
            sm += __shfl_xor_sync(0xffffffffu, sm, 2);
            if (tig == 0) s_red[(mw*32 + mi*16 + h*8 + gid)*8 + nw] = sm;
        }
    __syncthreads();
    if (tid < 64){
        float s = 0.f;
        #pragma unroll
        for (int k = 0; k < 8; k++) s += s_red[tid*8 + k];
        s_rzv[tid] = 1.0f / s;
    }
    __syncthreads();

    // normalized transposed store into padded smem [c][n], stride 68
    #pragma unroll
    for (int mi = 0; mi < 2; mi++)
        #pragma unroll
        for (int j = 0; j < 8; j++)
            #pragma unroll
            for (int v = 0; v < 4; v++){
                int col = nw*64 + j*8 + tig*2 + (v&1);
                int row = mw*32 + mi*16 + (v>>1)*8 + gid;
                s_t[col*68 + row] = acc[mi][j][v] * s_rzv[row];
            }
    __syncthreads();

    // vectorized coalesced fp16 copy-out: g_aff[b][c][nt*64 + n]
    __half* obase = g_aff + (size_t)b * CC * NN + (size_t)nt * 64;
    const int cpart = tid >> 4;           // 0..31
    const int n4    = (tid & 15) * 4;     // 0..60
    #pragma unroll 4
    for (int itc = 0; itc < 16; itc++){
        int c = itc*32 + cpart;
        float4 f = *reinterpret_cast<const float4*>(&s_t[c*68 + n4]);
        union { __half2 h[2]; uint2 u; } U;
        U.h[0] = __floats2half2_rn(f.x, f.y);
        U.h[1] = __floats2half2_rn(f.z, f.w);
        *reinterpret_cast<uint2*>(obase + (size_t)c * NN + n4) = U.u;
    }
}

// ================= kernel 4: top-16 over N per (b,c), blend ==================
// Values kept PACKED (2 fp16 per u32, order-preserving as u16) — 16 regs not 32.
// key = (fp16bits << 16) | (lane << 3) | chunk : one redux gives value+owner+chunk
__global__ void topk_kernel(float* __restrict__ out){
    int w    = (blockIdx.x * blockDim.x + threadIdx.x) >> 5;  // b*512 + c
    int lane = threadIdx.x & 31;
    if (w >= BB*CC) return;
    const uint4* p = reinterpret_cast<const uint4*>(g_aff + (size_t)w * NN);

    unsigned v16[16], ck[8];
    #pragma unroll
    for (int j = 0; j < 4; j++){
        uint4 q = p[j*32 + lane];
        v16[4*j+0] = q.x; v16[4*j+1] = q.y; v16[4*j+2] = q.z; v16[4*j+3] = q.w;
    }
    #pragma unroll
    for (int c = 0; c < 8; c++){
        unsigned m2 = __vmaxu2(v16[2*c], v16[2*c+1]);
        unsigned lo = m2 & 0xFFFFu, hi = m2 >> 16;
        unsigned mv = lo > hi ? lo : hi;
        ck[c] = (mv << 16) | ((unsigned)lane << 3) | (unsigned)c;
    }
    unsigned lk = ck[0];
    #pragma unroll
    for (int c = 1; c < 8; c++) lk = ck[c] > lk ? ck[c] : lk;

    float sum = 0.f;
    #pragma unroll
    for (int it = 0; it < KTOP; ++it){
        unsigned m;
        asm("redux.sync.max.u32 %0, %1, 0xffffffff;" : "=r"(m) : "r"(lk));
        __half_raw hr; hr.x = (unsigned short)(m >> 16);
        sum += __half2float(*reinterpret_cast<__half*>(&hr));
        if (((m >> 3) & 31u) == (unsigned)lane){
            unsigned val = m >> 16;
            int oc = (int)(m & 7u);
            #pragma unroll
            for (int c = 0; c < 8; c++) if (c == oc){
                if      ((v16[2*c]   & 0xFFFFu) == val) v16[2*c]   &= 0xFFFF0000u;
                else if ((v16[2*c]   >> 16)     == val) v16[2*c]   &= 0x0000FFFFu;
                else if ((v16[2*c+1] & 0xFFFFu) == val) v16[2*c+1] &= 0xFFFF0000u;
                else                                    v16[2*c+1] &= 0x0000FFFFu;
                unsigned m2 = __vmaxu2(v16[2*c], v16[2*c+1]);
                unsigned lo = m2 & 0xFFFFu, hi = m2 >> 16;
                unsigned mv = lo > hi ? lo : hi;
                ck[c] = (mv << 16) | ((unsigned)lane << 3) | (unsigned)c;
            }
            lk = ck[0];
            #pragma unroll
            for (int c = 1; c < 8; c++) lk = ck[c] > lk ? ck[c] : lk;
        }
    }
    if (lane == 0) out[w] += 0.7f * (sum * (1.0f / (float)KTOP));
}

// ================= launch =====================================================
extern "C" void kernel_launch(void* const* d_in, const int* in_sizes, int n_in,
                              void* d_out, int out_size){
    const float* vcls = nullptr;
    const float* vp   = nullptr;
    const float* text = nullptr;
    for (int i = 0; i < n_in; i++){
        if      (in_sizes[i] == BB*DD)     vcls = (const float*)d_in[i];
        else if (in_sizes[i] == BB*NN*DD)  vp   = (const float*)d_in[i];
        else if (in_sizes[i] == CC*DD)     text = (const float*)d_in[i];
    }
    float* out = (float*)d_out;

    cudaFuncSetAttribute(gemm_softmax_kernel,
                         cudaFuncAttributeMaxDynamicSharedMemorySize, SM_DYN);

    const int nwarps = CC + BB;
    convert_kernel<<<(nwarps*32 + 255)/256, 256>>>(vcls, text);
    affg_kernel<<<BB, 512>>>(vcls, out);
    gemm_softmax_kernel<<<1024, 512, SM_DYN>>>(vp);
    topk_kernel<<<(BB*CC*32 + 255)/256, 256>>>(out);
}

// round 13
// speedup vs baseline: 1.4780x; 1.0215x over previous
#include <cuda_runtime.h>
#include <cuda_fp16.h>
#include <math.h>
#include <stdint.h>

#define BB 64
#define NN 1024
#define DD 512
#define CC 512
#define KTOP 16
#define INV_TEMP (1.0f/0.07f)

// ---------------- scratch (device globals: no allocations allowed) ----------
__device__ __half g_aff[(size_t)BB * CC * NN];    // [b][c][n] normalized softmax p (fp16)
__device__ float g_rnt[CC];
__device__ float g_rnc[BB];
__device__ __half g_txh[(size_t)CC*DD];           // text fp16

// ================= helpers ====================================================
static __device__ __forceinline__ uint32_t smem_u32(const void* p){
    uint32_t a;
    asm("{ .reg .u64 t; cvta.to.shared.u64 t, %1; cvt.u32.u64 %0, t; }" : "=r"(a) : "l"(p));
    return a;
}
static __device__ __forceinline__ void cpasync16(uint32_t dst, const void* src){
    asm volatile("cp.async.cg.shared.global [%0], [%1], 16;" :: "r"(dst), "l"(src) : "memory");
}
static __device__ __forceinline__ uint32_t swz(uint32_t o){ return o ^ ((o >> 3) & 0x70u); }

static __device__ __forceinline__ void ldsm4(uint32_t &r0, uint32_t &r1,
                                             uint32_t &r2, uint32_t &r3, uint32_t addr){
    asm volatile("ldmatrix.sync.aligned.m8n8.x4.shared.b16 {%0,%1,%2,%3}, [%4];"
        : "=r"(r0), "=r"(r1), "=r"(r2), "=r"(r3) : "r"(addr));
}
static __device__ __forceinline__ void mma16816(float* d, const uint32_t* a,
                                                uint32_t b0, uint32_t b1){
    asm volatile("mma.sync.aligned.m16n8k16.row.col.f32.f16.f16.f32 "
        "{%0,%1,%2,%3}, {%4,%5,%6,%7}, {%8,%9}, {%0,%1,%2,%3};"
        : "+f"(d[0]), "+f"(d[1]), "+f"(d[2]), "+f"(d[3])
        : "r"(a[0]), "r"(a[1]), "r"(a[2]), "r"(a[3]), "r"(b0), "r"(b1));
}
static __device__ __forceinline__ unsigned umax2(unsigned a, unsigned b){ return a > b ? a : b; }

// ================= kernel 1: text fp16 convert + text/cls L2 norms ===========
__global__ void convert_kernel(const float* __restrict__ vcls,
                               const float* __restrict__ text){
    int w    = (blockIdx.x * blockDim.x + threadIdx.x) >> 5;
    int lane = threadIdx.x & 31;
    const int NW = CC + BB;
    if (w >= NW) return;
    const float* src; __half* hi = nullptr; float* rdst;
    if (w < CC){ src = text + (size_t)w*DD; hi = g_txh + (size_t)w*DD; rdst = g_rnt + w; }
    else       { int ci = w - CC; src = vcls + (size_t)ci*DD; rdst = g_rnc + ci; }
    float ss = 0.f;
    #pragma unroll
    for (int j = 0; j < 4; j++){
        int o = (j*32 + lane) * 4;
        float4 v = *reinterpret_cast<const float4*>(src + o);
        ss += v.x*v.x + v.y*v.y + v.z*v.z + v.w*v.w;
        if (hi){
            union { __half2 h2[2]; uint2 u; } P;
            P.h2[0] = __floats2half2_rn(v.x, v.y);
            P.h2[1] = __floats2half2_rn(v.z, v.w);
            *reinterpret_cast<uint2*>(hi + o) = P.u;
        }
    }
    #pragma unroll
    for (int off = 16; off; off >>= 1) ss += __shfl_xor_sync(0xffffffffu, ss, off);
    if (lane == 0) *rdst = 1.0f / fmaxf(sqrtf(ss), 1e-12f);
}

// ================= kernel 2: global affinity, writes 0.3*softmax ============
// text read as fp16 (g_txh) — runs after convert_kernel.
__global__ __launch_bounds__(512) void affg_kernel(const float* __restrict__ vcls,
                                                   float* __restrict__ out){
    __shared__ float sv[DD];
    __shared__ float red[16];
    int b = blockIdx.x, tid = threadIdx.x;
    sv[tid] = vcls[b*DD + tid];
    __syncthreads();
    const uint4* t4 = reinterpret_cast<const uint4*>(g_txh + (size_t)tid * DD);
    float dot = 0.f;
    #pragma unroll 8
    for (int k = 0; k < 64; k++){
        uint4 q = t4[k];
        float2 f0 = __half22float2(*reinterpret_cast<__half2*>(&q.x));
        float2 f1 = __half22float2(*reinterpret_cast<__half2*>(&q.y));
        float2 f2 = __half22float2(*reinterpret_cast<__half2*>(&q.z));
        float2 f3 = __half22float2(*reinterpret_cast<__half2*>(&q.w));
        const float* s = &sv[k*8];
        dot += f0.x*s[0] + f0.y*s[1] + f1.x*s[2] + f1.y*s[3]
             + f2.x*s[4] + f2.y*s[5] + f3.x*s[6] + f3.y*s[7];
    }
    float logit = dot * g_rnc[b] * g_rnt[tid] * INV_TEMP;
    int lane = tid & 31, wid = tid >> 5;
    float m = logit;
    #pragma unroll
    for (int off = 16; off; off >>= 1) m = fmaxf(m, __shfl_xor_sync(0xffffffffu, m, off));
    if (lane == 0) red[wid] = m;
    __syncthreads();
    float bm = red[0];
    #pragma unroll
    for (int i = 1; i < 16; i++) bm = fmaxf(bm, red[i]);
    __syncthreads();
    float e = __expf(logit - bm);
    float s = e;
    #pragma unroll
    for (int off = 16; off; off >>= 1) s += __shfl_xor_sync(0xffffffffu, s, off);
    if (lane == 0) red[wid] = s;
    __syncthreads();
    float bs = 0.f;
    #pragma unroll
    for (int i = 0; i < 16; i++) bs += red[i];
    out[b*CC + tid] = 0.3f * e / bs;
}

// ================= kernel 3: fp16 HMMA GEMM, 16 warps, fused A ==============
// CTA: 64 patches x 512 classes, 512 threads (16 warps: mw=wid>>3, nw=wid&7).
// Warp tile 32x64. kc=64, 8 k-iters. B triple-buffered, A double-buffered,
// head-barrier-only pipeline (loads issued AFTER the MMA region, no tail sync).
#define SM_A0   0u
#define SM_A1   8192u
#define SM_B0   16384u
#define SM_B1   81920u
#define SM_B2   147456u
#define SM_AUX  212992u
#define SM_DYN  (212992u + 4864u + 1024u)

static __device__ __forceinline__ void issueB(int kt, uint32_t b_dst, int tid){
    const __half* Bb = g_txh + kt * 64;
    #pragma unroll
    for (int t = 0; t < 8; t++){   // B: 512 rows x 128B = 4096 chunks / 512 thr
        int g = tid + t*512; int row = g >> 3; int c = g & 7;
        cpasync16(b_dst + swz(row*128 + c*16), Bb + (size_t)row*DD + c*8);
    }
    asm volatile("cp.async.commit_group;" ::: "memory");
}

// convert & store 2 rows' chunks of A (rows rw, rw+32; 16B chunk c16), sumsq
static __device__ __forceinline__ void stsA(uint32_t abase, int rw, int c16,
                                            const float4* pf, float* ss){
    #pragma unroll
    for (int i = 0; i < 2; i++){
        union { __half2 h2; uint32_t u; } P0, P1;
        P0.h2 = __floats2half2_rn(pf[i].x, pf[i].y);
        P1.h2 = __floats2half2_rn(pf[i].z, pf[i].w);
        ss[i] += pf[i].x*pf[i].x + pf[i].y*pf[i].y + pf[i].z*pf[i].z + pf[i].w*pf[i].w;
        uint32_t off = (uint32_t)((rw + 32*i)*128 + c16*8);
        asm volatile("st.shared.v2.b32 [%0], {%1,%2};"
            :: "r"(abase + swz(off)), "r"(P0.u), "r"(P1.u) : "memory");
    }
}

__global__ __launch_bounds__(512, 1) void gemm_softmax_kernel(const float* __restrict__ vp){
    extern __shared__ __align__(16) char dsm[];
    const uint32_t raw  = smem_u32(dsm);
    const uint32_t base = (raw + 1023u) & ~1023u;
    char* bp = dsm + (base - raw);

    const int tid = threadIdx.x;
    const int pb  = blockIdx.x;          // 0..1023
    const int b   = pb >> 4;
    const int nt  = pb & 15;

    const uint32_t ab[2]   = { base + SM_A0, base + SM_A1 };
    const uint32_t bbuf[3] = { base + SM_B0, base + SM_B1, base + SM_B2 };
    float* s_t    = reinterpret_cast<float*>(bp);                    // 512*68 f (overlays stages)
    float* s_rnt  = reinterpret_cast<float*>(bp + SM_AUX);           // 512 f
    float* s_rnp  = reinterpret_cast<float*>(bp + SM_AUX + 2048);    // 64 f
    float* s_red  = reinterpret_cast<float*>(bp + SM_AUX + 2304);    // 64*8 f
    float* s_gmax = reinterpret_cast<float*>(bp + SM_AUX + 4352);    // 64 f
    float* s_rzv  = reinterpret_cast<float*>(bp + SM_AUX + 4608);    // 64 f

    const int wid  = tid >> 5;
    const int lane = tid & 31;
    const int mw   = wid >> 3;           // 0..1
    const int nw   = wid & 7;            // 0..7
    const int gid  = lane >> 2;          // row group 0..7
    const int tig  = lane & 3;

    if (tid < 512) s_rnt[tid] = g_rnt[tid];

    // fused A path: 1024 float4 chunks per k-tile, 2 per thread (rows rw, rw+32)
    const int c16 = tid & 15;            // 16B chunk within 64-float slab row
    const int rw  = tid >> 4;            // row 0..31; second row = rw+32
    const float* Ag = vp + ((size_t)(pb*64 + rw))*DD + c16*4;

    float4 pf[2];
    pf[0] = *reinterpret_cast<const float4*>(Ag);
    pf[1] = *reinterpret_cast<const float4*>(Ag + (size_t)32*DD);

    issueB(0, bbuf[0], tid);
    issueB(1, bbuf[1], tid);

    float ss[2] = {0.f, 0.f};
    stsA(ab[0], rw, c16, pf, ss);                        // A tile for kt=0
    pf[0] = *reinterpret_cast<const float4*>(Ag + 64);
    pf[1] = *reinterpret_cast<const float4*>(Ag + (size_t)32*DD + 64);

    // ldmatrix lane addressing (canonical x4 fragment order)
    const int lr = (lane & 7) + ((lane >> 3) & 1) * 8;   // row within 16
    const int lk = (lane >> 4) * 16;                     // 16B col half

    float acc[2][8][4];
    #pragma unroll
    for (int mi = 0; mi < 2; mi++)
        #pragma unroll
        for (int j = 0; j < 8; j++)
            #pragma unroll
            for (int v = 0; v < 4; v++) acc[mi][j][v] = 0.f;

    int b3 = 0;                          // it % 3
    for (int it = 0; it < 8; ++it){
        if (it == 7) asm volatile("cp.async.wait_group 0;" ::: "memory");
        else         asm volatile("cp.async.wait_group 1;" ::: "memory");
        __syncthreads();                 // head barrier (the only one per iter)

        const uint32_t abase = ab[it & 1];
        const uint32_t bbase = bbuf[b3];
        #pragma unroll
        for (int ks = 0; ks < 4; ks++){
            uint32_t af[2][4];
            #pragma unroll
            for (int mi = 0; mi < 2; mi++){
                int r = mw*32 + mi*16 + lr;
                ldsm4(af[mi][0], af[mi][1], af[mi][2], af[mi][3],
                      abase + swz((uint32_t)(r*128 + ks*32 + lk)));
            }
            uint32_t bf[4][4];
            #pragma unroll
            for (int jj = 0; jj < 4; jj++){
                int r = nw*64 + jj*16 + lr;
                ldsm4(bf[jj][0], bf[jj][1], bf[jj][2], bf[jj][3],
                      bbase + swz((uint32_t)(r*128 + ks*32 + lk)));
            }
            #pragma unroll
            for (int mi = 0; mi < 2; mi++)
                #pragma unroll
                for (int j = 0; j < 8; j++)
                    mma16816(acc[mi][j], af[mi], bf[j>>1][j&1], bf[j>>1][(j&1)+2]);
        }
        // post-MMA, no tail barrier: write A for it+1 (buffer consumed at it-1),
        // issue B for it+2 into stage consumed at it-1 — both safe past head sync.
        if (it + 1 < 8) stsA(ab[(it+1)&1], rw, c16, pf, ss);
        if (it + 2 < 8){
            pf[0] = *reinterpret_cast<const float4*>(Ag + (it+2)*64);
            pf[1] = *reinterpret_cast<const float4*>(Ag + (size_t)32*DD + (it+2)*64);
            int nb = b3 + 2; if (nb >= 3) nb -= 3;
            issueB(it + 2, bbuf[nb], tid);
        }
        b3++; if (b3 >= 3) b3 -= 3;
    }
    __syncthreads();                     // stages dead; s_t overlay begins

    // patch norms: reduce sumsq over the 16-lane group sharing each row
    #pragma unroll
    for (int i = 0; i < 2; i++){
        float s = ss[i];
        s += __shfl_xor_sync(0xffffffffu, s, 1);
        s += __shfl_xor_sync(0xffffffffu, s, 2);
        s += __shfl_xor_sync(0xffffffffu, s, 4);
        s += __shfl_xor_sync(0xffffffffu, s, 8);
        if (c16 == 0) s_rnp[rw + 32*i] = 1.0f / fmaxf(sqrtf(s), 1e-12f);
    }
    __syncthreads();

    // ---- epilogue: scale, softmax over full 512 cols, normalized fp16 store
    float rs[2][2], rt[8][2];
    #pragma unroll
    for (int mi = 0; mi < 2; mi++)
        #pragma unroll
        for (int h = 0; h < 2; h++)
            rs[mi][h] = s_rnp[mw*32 + mi*16 + h*8 + gid] * INV_TEMP;
    #pragma unroll
    for (int j = 0; j < 8; j++){
        int c0 = nw*64 + j*8 + tig*2;
        rt[j][0] = s_rnt[c0]; rt[j][1] = s_rnt[c0+1];
    }
    #pragma unroll
    for (int mi = 0; mi < 2; mi++)
        #pragma unroll
        for (int j = 0; j < 8; j++)
            #pragma unroll
            for (int v = 0; v < 4; v++)
                acc[mi][j][v] *= rs[mi][v>>1] * rt[j][v&1];

    // per-row max (warp slice over its 64 cols), quad shuffle, 8-warp smem reduce
    #pragma unroll
    for (int mi = 0; mi < 2; mi++)
        #pragma unroll
        for (int h = 0; h < 2; h++){
            float mx = -3.0e38f;
            #pragma unroll
            for (int j = 0; j < 8; j++)
                mx = fmaxf(mx, fmaxf(acc[mi][j][2*h], acc[mi][j][2*h+1]));
            mx = fmaxf(mx, __shfl_xor_sync(0xffffffffu, mx, 1));
            mx = fmaxf(mx, __shfl_xor_sync(0xffffffffu, mx, 2));
            if (tig == 0) s_red[(mw*32 + mi*16 + h*8 + gid)*8 + nw] = mx;
        }
    __syncthreads();
    if (tid < 64){
        float m = s_red[tid*8];
        #pragma unroll
        for (int k = 1; k < 8; k++) m = fmaxf(m, s_red[tid*8 + k]);
        s_gmax[tid] = m;
    }
    __syncthreads();

    // exp + row sum
    #pragma unroll
    for (int mi = 0; mi < 2; mi++)
        #pragma unroll
        for (int h = 0; h < 2; h++){
            float gm = s_gmax[mw*32 + mi*16 + h*8 + gid];
            float sm = 0.f;
            #pragma unroll
            for (int j = 0; j < 8; j++){
                float e0 = __expf(acc[mi][j][2*h]   - gm);
                float e1 = __expf(acc[mi][j][2*h+1] - gm);
                acc[mi][j][2*h] = e0; acc[mi][j][2*h+1] = e1;
                sm += e0 + e1;
            }
            sm += __shfl_xor_sync(0xffffffffu, sm, 1);
            sm += __shfl_xor_sync(0xffffffffu, sm, 2);
            if (tig == 0) s_red[(mw*32 + mi*16 + h*8 + gid)*8 + nw] = sm;
        }
    __syncthreads();
    if (tid < 64){
        float s = 0.f;
        #pragma unroll
        for (int k = 0; k < 8; k++) s += s_red[tid*8 + k];
        s_rzv[tid] = 1.0f / s;
    }
    __syncthreads();

    // normalized transposed store into padded smem [c][n], stride 68
    #pragma unroll
    for (int mi = 0; mi < 2; mi++)
        #pragma unroll
        for (int j = 0; j < 8; j++)
            #pragma unroll
            for (int v = 0; v < 4; v++){
                int col = nw*64 + j*8 + tig*2 + (v&1);
                int row = mw*32 + mi*16 + (v>>1)*8 + gid;
                s_t[col*68 + row] = acc[mi][j][v] * s_rzv[row];
            }
    __syncthreads();

    // vectorized coalesced fp16 copy-out: g_aff[b][c][nt*64 + n]
    __half* obase = g_aff + (size_t)b * CC * NN + (size_t)nt * 64;
    const int cpart = tid >> 4;           // 0..31
    const int n4    = (tid & 15) * 4;     // 0..60
    #pragma unroll 4
    for (int itc = 0; itc < 16; itc++){
        int c = itc*32 + cpart;
        float4 f = *reinterpret_cast<const float4*>(&s_t[c*68 + n4]);
        union { __half2 h[2]; uint2 u; } U;
        U.h[0] = __floats2half2_rn(f.x, f.y);
        U.h[1] = __floats2half2_rn(f.z, f.w);
        *reinterpret_cast<uint2*>(obase + (size_t)c * NN + n4) = U.u;
    }
}

// ================= kernel 4: top-16 over N per (b,c), blend ==================
// Per-lane value + chunk-key arrays live in SMEM (warp-private, no barriers):
// owner update is ONE dynamically-indexed block instead of 8 guarded blocks.
// key = (fp16bits << 16) | (lane << 3) | chunk
__global__ __launch_bounds__(256) void topk_kernel(float* __restrict__ out){
    __shared__ uint32_t s_v[8][16][32];   // [warp][reg][lane]  values (reg-major)
    __shared__ uint32_t s_k[8][32][8];    // [warp][lane][chunk] keys (lane-major)

    const int wip  = threadIdx.x >> 5;                  // warp in block
    const int lane = threadIdx.x & 31;
    const int w    = blockIdx.x * 8 + wip;              // b*512 + c
    if (w >= BB*CC) return;
    const uint4* p = reinterpret_cast<const uint4*>(g_aff + (size_t)w * NN);

    uint32_t (*V)[32] = s_v[wip];
    uint32_t* K = s_k[wip][lane];

    unsigned lk = 0;
    #pragma unroll
    for (int j = 0; j < 4; j++){
        uint4 q = p[j*32 + lane];
        V[4*j+0][lane] = q.x; V[4*j+1][lane] = q.y;
        V[4*j+2][lane] = q.z; V[4*j+3][lane] = q.w;
        unsigned m0 = __vmaxu2(q.x, q.y);
        unsigned mv0 = umax2(m0 & 0xFFFFu, m0 >> 16);
        unsigned k0 = (mv0 << 16) | ((unsigned)lane << 3) | (unsigned)(2*j);
        unsigned m1 = __vmaxu2(q.z, q.w);
        unsigned mv1 = umax2(m1 & 0xFFFFu, m1 >> 16);
        unsigned k1 = (mv1 << 16) | ((unsigned)lane << 3) | (unsigned)(2*j + 1);
        K[2*j] = k0; K[2*j+1] = k1;
        lk = umax2(lk, umax2(k0, k1));
    }

    float sum = 0.f;
    #pragma unroll
    for (int it = 0; it < KTOP; ++it){
        unsigned m;
        asm("redux.sync.max.u32 %0, %1, 0xffffffff;" : "=r"(m) : "r"(lk));
        __half_raw hr; hr.x = (unsigned short)(m >> 16);
        sum += __half2float(*reinterpret_cast<__half*>(&hr));
        if (((m >> 3) & 31u) == (unsigned)lane){
            const unsigned val = m >> 16;
            const int oc = (int)(m & 7u);
            unsigned v0 = V[2*oc  ][lane];
            unsigned v1 = V[2*oc+1][lane];
            if      ((v0 & 0xFFFFu) == val) v0 &= 0xFFFF0000u;
            else if ((v0 >> 16)     == val) v0 &= 0x0000FFFFu;
            else if ((v1 & 0xFFFFu) == val) v1 &= 0xFFFF0000u;
            else                            v1 &= 0x0000FFFFu;
            V[2*oc  ][lane] = v0;
            V[2*oc+1][lane] = v1;
            unsigned m2 = __vmaxu2(v0, v1);
            unsigned mv = umax2(m2 & 0xFFFFu, m2 >> 16);
            K[oc] = (mv << 16) | ((unsigned)lane << 3) | (unsigned)oc;
            uint4 ka = *reinterpret_cast<uint4*>(&K[0]);
            uint4 kb = *reinterpret_cast<uint4*>(&K[4]);
            unsigned t0 = umax2(ka.x, ka.y), t1 = umax2(ka.z, ka.w);
            unsigned t2 = umax2(kb.x, kb.y), t3 = umax2(kb.z, kb.w);
            lk = umax2(umax2(t0, t1), umax2(t2, t3));
        }
    }
    if (lane == 0) out[w] += 0.7f * (sum * (1.0f / (float)KTOP));
}

// ================= launch =====================================================
extern "C" void kernel_launch(void* const* d_in, const int* in_sizes, int n_in,
                              void* d_out, int out_size){
    const float* vcls = nullptr;
    const float* vp   = nullptr;
    const float* text = nullptr;
    for (int i = 0; i < n_in; i++){
        if      (in_sizes[i] == BB*DD)     vcls = (const float*)d_in[i];
        else if (in_sizes[i] == BB*NN*DD)  vp   = (const float*)d_in[i];
        else if (in_sizes[i] == CC*DD)     text = (const float*)d_in[i];
    }
    float* out = (float*)d_out;

    cudaFuncSetAttribute(gemm_softmax_kernel,
                         cudaFuncAttributeMaxDynamicSharedMemorySize, SM_DYN);

    const int nwarps = CC + BB;
    convert_kernel<<<(nwarps*32 + 255)/256, 256>>>(vcls, text);
    affg_kernel<<<BB, 512>>>(vcls, out);
    gemm_softmax_kernel<<<1024, 512, SM_DYN>>>(vp);
    topk_kernel<<<(BB*CC)/8, 256>>>(out);
}